// round 10
// baseline (speedup 1.0000x reference)
#include <cuda_runtime.h>

#define T_LEN 1024
#define BATCH 4
#define EMB   1024
#define NH    16
#define HD    64
#define BH    (BATCH*NH)   // 64
#define NREL  33           // 2L+1

// Scratch (static device arrays: allocation-free per harness rules)
__device__ float g_q[BH * T_LEN * HD];        // tf32 bits, pre-scaled by 0.125*log2e
__device__ float g_k[BH * T_LEN * HD];        // tf32 bits
__device__ float g_v[BH * HD * T_LEN];        // tf32 bits, TRANSPOSED [bh][d][t]
__device__ float g_attn[T_LEN * BATCH * EMB]; // tf32 bits, [t*4+b][e]
__device__ float g_qin[4096 * 1024];          // tf32(query)
__device__ float g_win[3072 * 1024];          // tf32(w_in)
__device__ float g_wout[1024 * 1024];         // tf32(w_out)

__device__ __forceinline__ unsigned f2tf(float f) {
    unsigned u;
    asm("cvt.rna.tf32.f32 %0, %1;" : "=r"(u) : "f"(f));
    return u;
}

__device__ __forceinline__ float ex2(float x) {
    float y;
    asm("ex2.approx.ftz.f32 %0, %1;" : "=f"(y) : "f"(x));
    return y;
}

// D += A @ B  (m16n8k8, tf32 in, fp32 accum). c aliases d.
__device__ __forceinline__ void mma8(float* c, const unsigned* a, const unsigned* b) {
    asm volatile(
        "mma.sync.aligned.m16n8k8.row.col.f32.tf32.tf32.f32 "
        "{%0,%1,%2,%3}, {%4,%5,%6,%7}, {%8,%9}, {%0,%1,%2,%3};\n"
        : "+f"(c[0]), "+f"(c[1]), "+f"(c[2]), "+f"(c[3])
        : "r"(a[0]), "r"(a[1]), "r"(a[2]), "r"(a[3]), "r"(b[0]), "r"(b[1]));
}

__device__ __forceinline__ unsigned smem_u32(const void* p) {
    return (unsigned)__cvta_generic_to_shared(p);
}

__device__ __forceinline__ void ldsm4(unsigned* d, unsigned addr) {
    asm volatile(
        "ldmatrix.sync.aligned.m8n8.x4.shared.b16 {%0,%1,%2,%3}, [%4];"
        : "=r"(d[0]), "=r"(d[1]), "=r"(d[2]), "=r"(d[3]) : "r"(addr));
}

__device__ __forceinline__ void cpa16(unsigned dst, const void* src) {
    asm volatile("cp.async.cg.shared.global [%0], [%1], 16;"
                 :: "r"(dst), "l"(src));
}

// ---------------------------------------------------------------------------
// Elementwise fp32 -> tf32(rna) pre-conversion (bits stored in float array).
// ---------------------------------------------------------------------------
__global__ void __launch_bounds__(256)
cvt_tf32(const float* __restrict__ in, float* __restrict__ out_, int n4)
{
    const int i = blockIdx.x * 256 + threadIdx.x;
    if (i < n4) {
        float4 v = ((const float4*)in)[i];
        uint4 u = make_uint4(f2tf(v.x), f2tf(v.y), f2tf(v.z), f2tf(v.w));
        ((uint4*)out_)[i] = u;
    }
}

// ---------------------------------------------------------------------------
// TC GEMM v2: C[M,N] = A[M,K] * B[N,K]^T + bias[N].  tf32 bits in A,B.
// 128-thread CTAs (4 warps, 2x2 grid of 64x64 warp tiles), block 128x128,
// K-chunk 32, cp.async 2-stage pipeline, LDSM fragments, 2 CTAs/SM.
// 128 B of smem traffic per MMA (was 192).
// mode 0: scatter q/k/v (q scaled by 0.125*log2e, V transposed). mode 1: Cout.
// ---------------------------------------------------------------------------
#define GSTG (128 * 36)          // dwords per matrix per stage
#define GSTGB (GSTG * 4)         // bytes

__global__ void __launch_bounds__(128)
gemm_tc(const float* __restrict__ A, const float* __restrict__ B,
        const float* __restrict__ bias, float* __restrict__ Cout,
        int M, int N, int K, int mode)
{
    extern __shared__ unsigned sh[];
    unsigned* As = sh;               // [2][128*36], stride 36 (≡4 mod 32)
    unsigned* Bs = sh + 2 * GSTG;

    const int tid  = threadIdx.x;
    const int lane = tid & 31;
    const int warp = tid >> 5;          // 0..3
    const int wm   = (warp & 1) * 64;
    const int wn   = (warp >> 1) * 64;
    const int row0 = blockIdx.y * 128;
    const int col0 = blockIdx.x * 128;

    // ldmatrix lane address bases (bytes, stage 0)
    const int lrow = lane & 7;
    const int lb3  = (lane >> 3) & 1;
    const int lb4  = lane >> 4;
    unsigned aAddr[4], bAddr[4];
#pragma unroll
    for (int mf = 0; mf < 4; mf++)
        aAddr[mf] = smem_u32(&As[(wm + mf * 16 + lrow + lb3 * 8) * 36 + lb4 * 4]);
#pragma unroll
    for (int np = 0; np < 4; np++)
        bAddr[np] = smem_u32(&Bs[(wn + np * 16 + lb4 * 8 + lrow) * 36 + lb3 * 4]);

    const unsigned aSm = smem_u32(As);
    const unsigned bSm = smem_u32(Bs);

    float acc[4][8][4];
#pragma unroll
    for (int mf = 0; mf < 4; mf++)
#pragma unroll
        for (int nt = 0; nt < 8; nt++)
#pragma unroll
            for (int f = 0; f < 4; f++) acc[mf][nt][f] = 0.0f;

    const unsigned* aP = (const unsigned*)A + (size_t)row0 * K;
    const unsigned* bP = (const unsigned*)B + (size_t)col0 * K;

    // cp.async tile issue: 1024 16B-segments per matrix, 8 per thread
    // i = tid + 128*it : r = i>>3 (0..127), c4 = (i&7)*4
    auto issue = [&](int k0, int st) {
        const unsigned aDst = aSm + (unsigned)st * GSTGB;
        const unsigned bDst = bSm + (unsigned)st * GSTGB;
#pragma unroll
        for (int it = 0; it < 8; it++) {
            const int i = tid + 128 * it;
            const int r = i >> 3, c4 = (i & 7) * 4;
            const unsigned doff = (unsigned)(r * 36 + c4) * 4;
            cpa16(aDst + doff, aP + (size_t)r * K + k0 + c4);
            cpa16(bDst + doff, bP + (size_t)r * K + k0 + c4);
        }
        asm volatile("cp.async.commit_group;");
    };

    issue(0, 0);

    const int nC = K >> 5;
    for (int c = 0; c < nC; c++) {
        const int st = c & 1;
        const unsigned soff = (unsigned)st * GSTGB;

        if (c + 1 < nC) {
            issue((c + 1) * 32, st ^ 1);
            asm volatile("cp.async.wait_group 1;");
        } else {
            asm volatile("cp.async.wait_group 0;");
        }
        __syncthreads();     // chunk c resident for all warps

#pragma unroll
        for (int ks = 0; ks < 4; ks++) {
            const unsigned ko = soff + ks * 32;
            unsigned a[4][4];
#pragma unroll
            for (int mf = 0; mf < 4; mf++) ldsm4(a[mf], aAddr[mf] + ko);
#pragma unroll
            for (int np = 0; np < 4; np++) {
                unsigned bf[4];
                ldsm4(bf, bAddr[np] + ko);
#pragma unroll
                for (int mf = 0; mf < 4; mf++) {
                    mma8(acc[mf][2 * np],     a[mf], &bf[0]);
                    mma8(acc[mf][2 * np + 1], a[mf], &bf[2]);
                }
            }
        }
        __syncthreads();     // all warps done with stage st before refill
    }

    // epilogue
    const int q4 = lane & 3;
    const int g8 = lane >> 2;
#pragma unroll
    for (int mf = 0; mf < 4; mf++) {
#pragma unroll
        for (int rr = 0; rr < 2; rr++) {
            const int m = row0 + wm + mf * 16 + g8 + rr * 8;
#pragma unroll
            for (int nt = 0; nt < 8; nt++) {
#pragma unroll
                for (int cc = 0; cc < 2; cc++) {
                    const int n = col0 + wn + nt * 8 + 2 * q4 + cc;
                    float v = acc[mf][nt][rr * 2 + cc] + bias[n];
                    if (mode == 0) {
                        const int sec = n >> 10;
                        const int e = n & 1023;
                        const int h = e >> 6, d = e & 63;
                        const int t = m >> 2, b = m & 3;
                        const int bh = b * NH + h;
                        if (sec == 0)  // 0.125 * log2(e)
                            g_q[(bh * T_LEN + t) * HD + d] =
                                __uint_as_float(f2tf(v * 0.18033688f));
                        else if (sec == 1)
                            g_k[(bh * T_LEN + t) * HD + d] =
                                __uint_as_float(f2tf(v));
                        else  // V transposed: [bh][d][t]
                            g_v[((size_t)bh * HD + d) * T_LEN + t] =
                                __uint_as_float(f2tf(v));
                    } else {
                        Cout[(size_t)m * N + n] = v;
                    }
                }
            }
        }
    }
}

// ---------------------------------------------------------------------------
// Flash attention (validated round-9 version): 64-row q-tiles, 4 warps x 16
// rows, register K/V prefetch, 2 CTAs/SM, base-2 softmax, saturation fast
// path, MMA qr prologue. grid = (16 q-tiles, 64 heads), 128 threads.
// ---------------------------------------------------------------------------
__global__ void __launch_bounds__(128)
attn_tc(const float* __restrict__ relk)
{
    extern __shared__ float sm[];
    unsigned* Qs = (unsigned*)sm;             // [64][68]  rows=t, cols=d
    unsigned* Ks = Qs + 64 * 68;              // [64][68]  rows=s, cols=d
    unsigned* Vs = Ks + 64 * 68;              // [64][68]  rows=d, cols=s
    unsigned* Ps = Vs + 64 * 68;              // [64][68]  rows=t, cols=s
    float* qrs   = (float*)(Ps + 64 * 68);    // [64][33]
    unsigned* rels = Ps;                      // tf32 overlay [64][68], rows>=33 zero

    const int tid  = threadIdx.x;
    const int lane = tid & 31;
    const int warp = tid >> 5;                // 0..3
    const int q4   = lane & 3;
    const int g8   = lane >> 2;               // 0..7
    const int bh   = blockIdx.y;
    const int tq0  = blockIdx.x * 64;
    const int m0   = warp * 16;

    const int lrow = lane & 7;
    const int lb3  = (lane >> 3) & 1;
    const int lb4  = lane >> 4;
    const unsigned qAddr = smem_u32(&Qs[(m0 + lrow + lb3 * 8) * 68 + lb4 * 4]);
    const unsigned pAddr = smem_u32(&Ps[(m0 + lrow + lb3 * 8) * 68 + lb4 * 4]);
    unsigned kAddr[4], vAddr[4], relAddr[3];
#pragma unroll
    for (int np = 0; np < 4; np++) {
        kAddr[np] = smem_u32(&Ks[(np * 16 + lb4 * 8 + lrow) * 68 + lb3 * 4]);
        vAddr[np] = smem_u32(&Vs[(np * 16 + lb4 * 8 + lrow) * 68 + lb3 * 4]);
    }
#pragma unroll
    for (int np = 0; np < 3; np++)
        relAddr[np] = smem_u32(&rels[(np * 16 + lb4 * 8 + lrow) * 68 + lb3 * 4]);

    // load Q tile (64x64, already tf32)
    {
        const uint4* qb = (const uint4*)(g_q + (size_t)(bh * T_LEN + tq0) * HD);
#pragma unroll 2
        for (int i = tid; i < 1024; i += 128)
            *(uint4*)&Qs[(i >> 4) * 68 + (i & 15) * 4] = qb[i];
    }
    // relation keys (tf32) into Ps overlay; rows 33..63 zero
    for (int i = tid; i < 64 * 68; i += 128) rels[i] = 0u;
    __syncthreads();
    for (int i = tid; i < NREL * 64; i += 128) {
        const int j = i >> 6, d = i & 63;
        rels[j * 68 + d] = f2tf(relk[j * EMB + d]);
    }
    __syncthreads();

    // qr[r][j] = q[r] . rel[j] via MMA (j in 0..47, keep j<33)
    {
        float sq[6][4];
#pragma unroll
        for (int nt = 0; nt < 6; nt++)
#pragma unroll
            for (int f = 0; f < 4; f++) sq[nt][f] = 0.0f;
#pragma unroll
        for (int ks = 0; ks < 8; ks++) {
            const unsigned ko = ks * 32;
            unsigned a[4];
            ldsm4(a, qAddr + ko);
#pragma unroll
            for (int np = 0; np < 3; np++) {
                unsigned bf[4];
                ldsm4(bf, relAddr[np] + ko);
                mma8(sq[2 * np],     a, &bf[0]);
                mma8(sq[2 * np + 1], a, &bf[2]);
            }
        }
#pragma unroll
        for (int rid = 0; rid < 2; rid++) {
            const int rloc = m0 + rid * 8 + g8;
#pragma unroll
            for (int nt = 0; nt < 6; nt++)
#pragma unroll
                for (int cc = 0; cc < 2; cc++) {
                    const int j = nt * 8 + 2 * q4 + cc;
                    if (j < NREL) qrs[rloc * NREL + j] = sq[nt][rid * 2 + cc];
                }
        }
    }

    const uint4* kbase = (const uint4*)(g_k + (size_t)bh * T_LEN * HD);
    const float* vbase = g_v + (size_t)bh * HD * T_LEN;   // [d][t]

    // prefetch tile 0 into registers
    uint4 pk[8], pv[8];
#pragma unroll
    for (int it = 0; it < 8; it++) {
        const int i = tid + 128 * it;
        const int r = i >> 4, c4 = (i & 15) * 4;
        pk[it] = kbase[i];
        pv[it] = *(const uint4*)(vbase + (size_t)r * T_LEN + c4);
    }

    float o[8][4];
#pragma unroll
    for (int nt = 0; nt < 8; nt++)
#pragma unroll
        for (int f = 0; f < 4; f++) o[nt][f] = 0.0f;
    float mrow[2] = {-1e30f, -1e30f};
    float lrw[2]  = {0.0f, 0.0f};

    __syncthreads();   // qr writes visible; rel overlay consumption complete

    for (int kt = 0; kt < 16; kt++) {
        const int s0 = kt * 64;

        // store prefetched tile: Ks rows=s cols=d; Vs rows=d cols=s
#pragma unroll
        for (int it = 0; it < 8; it++) {
            const int i = tid + 128 * it;
            const int r = i >> 4, c4 = (i & 15) * 4;
            *(uint4*)&Ks[r * 68 + c4] = pk[it];
            *(uint4*)&Vs[r * 68 + c4] = pv[it];
        }
        __syncthreads();

        // prefetch next tile
        if (kt + 1 < 16) {
            const uint4* kb = kbase + (size_t)(s0 + 64) * (HD / 4);
#pragma unroll
            for (int it = 0; it < 8; it++) {
                const int i = tid + 128 * it;
                const int r = i >> 4, c4 = (i & 15) * 4;
                pk[it] = kb[i];
                pv[it] = *(const uint4*)(vbase + (size_t)r * T_LEN + s0 + 64 + c4);
            }
        }

        // S = Q @ K^T  (warp's 16 rows x 64 cols) — all via ldmatrix
        float s[8][4];
#pragma unroll
        for (int nt = 0; nt < 8; nt++)
#pragma unroll
            for (int f = 0; f < 4; f++) s[nt][f] = 0.0f;

#pragma unroll
        for (int ks = 0; ks < 8; ks++) {
            const unsigned ko = ks * 32;
            unsigned a[4];
            ldsm4(a, qAddr + ko);
#pragma unroll
            for (int np = 0; np < 4; np++) {
                unsigned bf[4];
                ldsm4(bf, kAddr[np] + ko);
                mma8(s[2 * np],     a, &bf[0]);
                mma8(s[2 * np + 1], a, &bf[2]);
            }
        }

        // bias + online softmax, base-2 (2 rows/lane; 4 lanes/row: xor 1,2)
#pragma unroll
        for (int rid = 0; rid < 2; rid++) {
            const int rloc = m0 + rid * 8 + g8;
            const int rg = tq0 + rloc;
            const float* qr = &qrs[rloc * NREL];
            float vals[16];
            float mx = -1e30f;
            if (s0 - rg >= 16) {               // whole tile right-saturated
                const float b32 = qr[32];
#pragma unroll
                for (int nt = 0; nt < 8; nt++)
#pragma unroll
                    for (int cc = 0; cc < 2; cc++) {
                        float v = s[nt][rid * 2 + cc] + b32;
                        vals[nt * 2 + cc] = v;
                        mx = fmaxf(mx, v);
                    }
            } else if (rg - s0 >= 79) {        // whole tile left-saturated
                const float b0 = qr[0];
#pragma unroll
                for (int nt = 0; nt < 8; nt++)
#pragma unroll
                    for (int cc = 0; cc < 2; cc++) {
                        float v = s[nt][rid * 2 + cc] + b0;
                        vals[nt * 2 + cc] = v;
                        mx = fmaxf(mx, v);
                    }
            } else {
#pragma unroll
                for (int nt = 0; nt < 8; nt++)
#pragma unroll
                    for (int cc = 0; cc < 2; cc++) {
                        const int sg = s0 + nt * 8 + 2 * q4 + cc;
                        int delta = min(max(sg - rg, -16), 16) + 16;
                        float v = s[nt][rid * 2 + cc] + qr[delta];
                        vals[nt * 2 + cc] = v;
                        mx = fmaxf(mx, v);
                    }
            }
            mx = fmaxf(mx, __shfl_xor_sync(0xffffffffu, mx, 1));
            mx = fmaxf(mx, __shfl_xor_sync(0xffffffffu, mx, 2));
            const float mnew = fmaxf(mrow[rid], mx);
            const float alpha = ex2(mrow[rid] - mnew);
            float rs = 0.0f;
#pragma unroll
            for (int j = 0; j < 16; j++) {
                vals[j] = ex2(vals[j] - mnew);
                rs += vals[j];
            }
            rs += __shfl_xor_sync(0xffffffffu, rs, 1);
            rs += __shfl_xor_sync(0xffffffffu, rs, 2);
            lrw[rid] = lrw[rid] * alpha + rs;
            mrow[rid] = mnew;
#pragma unroll
            for (int nt = 0; nt < 8; nt++) {
                o[nt][rid * 2]     *= alpha;
                o[nt][rid * 2 + 1] *= alpha;
            }
#pragma unroll
            for (int nt = 0; nt < 8; nt++) {
                const int cpos = nt * 8 + 2 * q4;
                uint2 pw = make_uint2(f2tf(vals[nt * 2]), f2tf(vals[nt * 2 + 1]));
                *(uint2*)&Ps[rloc * 68 + cpos] = pw;
            }
        }
        __syncwarp();   // P produced/consumed within this warp only

        // O += P @ V  (P and V via ldmatrix; Vs rows=d(n), cols=s(k))
#pragma unroll
        for (int ks = 0; ks < 8; ks++) {
            const unsigned ko = ks * 32;
            unsigned a[4];
            ldsm4(a, pAddr + ko);
#pragma unroll
            for (int np = 0; np < 4; np++) {
                unsigned vf[4];
                ldsm4(vf, vAddr[np] + ko);
                mma8(o[2 * np],     a, &vf[0]);
                mma8(o[2 * np + 1], a, &vf[2]);
            }
        }
        __syncthreads();   // done reading Ks/Vs; safe to overwrite next iter
    }

    // write attn (tf32 bits) in [t][b][e] layout
    const int b = bh >> 4, h = bh & 15;
#pragma unroll
    for (int rid = 0; rid < 2; rid++) {
        const int t = tq0 + m0 + rid * 8 + g8;
        const float inv = 1.0f / lrw[rid];
#pragma unroll
        for (int nt = 0; nt < 8; nt++) {
            const int d = nt * 8 + 2 * q4;
            uint2 w = make_uint2(f2tf(o[nt][rid * 2] * inv),
                                 f2tf(o[nt][rid * 2 + 1] * inv));
            *(uint2*)&g_attn[(t * BATCH + b) * EMB + h * HD + d] = w;
        }
    }
}

// ---------------------------------------------------------------------------
extern "C" void kernel_launch(void* const* d_in, const int* in_sizes, int n_in,
                              void* d_out, int out_size)
{
    (void)in_sizes; (void)n_in; (void)out_size;
    const float* query = (const float*)d_in[0];   // [T,B,E]
    const float* w_in  = (const float*)d_in[1];   // [3E,E]
    const float* b_in  = (const float*)d_in[2];   // [3E]
    const float* relk  = (const float*)d_in[3];   // [33,E]
    const float* w_out = (const float*)d_in[4];   // [E,E]
    const float* b_out = (const float*)d_in[5];   // [E]
    float* out = (float*)d_out;                   // [T,B,E]

    float *qin, *win, *wout, *attn_ptr;
    cudaGetSymbolAddress((void**)&qin,  g_qin);
    cudaGetSymbolAddress((void**)&win,  g_win);
    cudaGetSymbolAddress((void**)&wout, g_wout);
    cudaGetSymbolAddress((void**)&attn_ptr, g_attn);

    // 0) one-time tf32 pre-conversion of fp32 operands
    cvt_tf32<<<4096, 256>>>(query, qin, 4096 * 1024 / 4);
    cvt_tf32<<<3072, 256>>>(w_in,  win, 3072 * 1024 / 4);
    cvt_tf32<<<1024, 256>>>(w_out, wout, 1024 * 1024 / 4);

    const size_t gemm_smem = (size_t)4 * GSTG * sizeof(unsigned);  // 73728 B
    cudaFuncSetAttribute(gemm_tc,
                         cudaFuncAttributeMaxDynamicSharedMemorySize,
                         (int)gemm_smem);

    // 1) fused QKV projection -> tf32 head-major q/k/v (V transposed)
    gemm_tc<<<dim3(24, 32), 128, gemm_smem>>>(
        qin, win, b_in, nullptr, 4096, 3072, 1024, 0);

    // 2) flash attention with relative bias
    const size_t attn_smem =
        (size_t)(4 * 64 * 68 + 64 * NREL) * sizeof(float);   // 78080 B
    cudaFuncSetAttribute(attn_tc,
                         cudaFuncAttributeMaxDynamicSharedMemorySize,
                         (int)attn_smem);
    attn_tc<<<dim3(16, 64), 128, attn_smem>>>(relk);

    // 3) output projection (writes fp32 final output)
    gemm_tc<<<dim3(8, 32), 128, gemm_smem>>>(
        attn_ptr, wout, b_out, out, 4096, 1024, 1024, 1);
}

// round 11
// speedup vs baseline: 1.7866x; 1.7866x over previous
#include <cuda_runtime.h>
#include <cuda_fp16.h>

#define T_LEN 1024
#define BATCH 4
#define EMB   1024
#define NH    16
#define HD    64
#define BH    (BATCH*NH)   // 64
#define NREL  33           // 2L+1

// Scratch (static device arrays: allocation-free per harness rules)
__device__ __half g_q[BH * T_LEN * HD];        // fp16, pre-scaled by 0.125*log2e
__device__ __half g_k[BH * T_LEN * HD];        // fp16
__device__ __half g_v[BH * HD * T_LEN];        // fp16, TRANSPOSED [bh][d][t]
__device__ __half g_attn[T_LEN * BATCH * EMB]; // fp16, [t*4+b][e]
__device__ __half g_qin[4096 * 1024];          // fp16(query)
__device__ __half g_win[3072 * 1024];          // fp16(w_in)
__device__ __half g_wout[1024 * 1024];         // fp16(w_out)

__device__ __forceinline__ float ex2(float x) {
    float y;
    asm("ex2.approx.ftz.f32 %0, %1;" : "=f"(y) : "f"(x));
    return y;
}

// D += A @ B  (m16n8k16, fp16 in, fp32 accum). c aliases d.
__device__ __forceinline__ void mma16(float* c, const unsigned* a, const unsigned* b) {
    asm volatile(
        "mma.sync.aligned.m16n8k16.row.col.f32.f16.f16.f32 "
        "{%0,%1,%2,%3}, {%4,%5,%6,%7}, {%8,%9}, {%0,%1,%2,%3};\n"
        : "+f"(c[0]), "+f"(c[1]), "+f"(c[2]), "+f"(c[3])
        : "r"(a[0]), "r"(a[1]), "r"(a[2]), "r"(a[3]), "r"(b[0]), "r"(b[1]));
}

__device__ __forceinline__ unsigned smem_u32(const void* p) {
    return (unsigned)__cvta_generic_to_shared(p);
}

// 4x (8x8 b16) tiles. A frag (m16k16): tiles m0k0,m8k0,m0k8,m8k8.
// B frag pair (two n8k16): tiles n0k0,n0k8,n8k0,n8k8.
__device__ __forceinline__ void ldsm4(unsigned* d, unsigned addr) {
    asm volatile(
        "ldmatrix.sync.aligned.m8n8.x4.shared.b16 {%0,%1,%2,%3}, [%4];"
        : "=r"(d[0]), "=r"(d[1]), "=r"(d[2]), "=r"(d[3]) : "r"(addr));
}

// ---------------------------------------------------------------------------
// Elementwise fp32 -> fp16(rn) pre-conversion.
// ---------------------------------------------------------------------------
__global__ void __launch_bounds__(256)
cvt_f16(const float* __restrict__ in, __half* __restrict__ out_, int n4)
{
    const int i = blockIdx.x * 256 + threadIdx.x;
    if (i < n4) {
        float4 v = ((const float4*)in)[i];
        __half2 h0 = __floats2half2_rn(v.x, v.y);
        __half2 h1 = __floats2half2_rn(v.z, v.w);
        ((__half2*)out_)[2 * i]     = h0;
        ((__half2*)out_)[2 * i + 1] = h1;
    }
}

// ---------------------------------------------------------------------------
// FP16 TC GEMM: C[M,N] = A[M,K] * B[N,K]^T + bias[N].  K in fp16 elements.
// Block 128x128, K-chunk 64, 8 warps (32m x 64n tiles), 2-stage register-
// prefetch smem pipeline (round-9 pattern), 2 CTAs/SM. Row stride 36 words
// (72 halves): LDSM rows hit banks 0,4,..28 -> conflict-free.
// mode 0: scatter q/k/v fp16 (q scaled by 0.125*log2e, V transposed).
// mode 1: write fp32 Cout.
// ---------------------------------------------------------------------------
#define GSTG (128 * 36)          // words per matrix per stage

__global__ void __launch_bounds__(256, 2)
gemm_tc(const __half* __restrict__ A, const __half* __restrict__ B,
        const float* __restrict__ bias, float* __restrict__ Cout,
        int M, int N, int K, int mode)
{
    extern __shared__ unsigned sh[];
    unsigned* As = sh;               // [2][128*36] words
    unsigned* Bs = sh + 2 * GSTG;

    const int tid  = threadIdx.x;
    const int lane = tid & 31;
    const int warp = tid >> 5;
    const int wm   = (warp & 3) * 32;
    const int wn   = (warp >> 2) * 64;
    const int row0 = blockIdx.y * 128;
    const int col0 = blockIdx.x * 128;

    // ldmatrix lane address bases (bytes, stage 0); offsets in halves:
    // A row = m + lb3*8, col = lb4*8 halves (= lb4*4 words)
    // B row = n + lb4*8, col = lb3*8 halves
    const int lrow = lane & 7;
    const int lb3  = (lane >> 3) & 1;
    const int lb4  = lane >> 4;
    unsigned aAddr[2], bAddr[4];
#pragma unroll
    for (int mt = 0; mt < 2; mt++)
        aAddr[mt] = smem_u32(&As[(wm + mt * 16 + lrow + lb3 * 8) * 36 + lb4 * 4]);
#pragma unroll
    for (int np = 0; np < 4; np++)
        bAddr[np] = smem_u32(&Bs[(wn + np * 16 + lb4 * 8 + lrow) * 36 + lb3 * 4]);

    float acc[2][8][4];
#pragma unroll
    for (int mt = 0; mt < 2; mt++)
#pragma unroll
        for (int nt = 0; nt < 8; nt++)
#pragma unroll
            for (int f = 0; f < 4; f++) acc[mt][nt][f] = 0.0f;

    const __half* aP = A + (size_t)row0 * K;
    const __half* bP = B + (size_t)col0 * K;

    // chunk = 128 rows x 64 halves = 1024 uint4 per matrix; 4 per thread.
    // i = tid + 256*it : r = i>>3, c8 = (i&7)*8 halves
    uint4 pa[4], pb[4];
#pragma unroll
    for (int it = 0; it < 4; it++) {
        const int i = tid + 256 * it;
        const int r = i >> 3, c8 = (i & 7) * 8;
        pa[it] = *(const uint4*)(aP + (size_t)r * K + c8);
        pb[it] = *(const uint4*)(bP + (size_t)r * K + c8);
    }
#pragma unroll
    for (int it = 0; it < 4; it++) {
        const int i = tid + 256 * it;
        const int r = i >> 3, w4 = (i & 7) * 4;
        *(uint4*)&As[r * 36 + w4] = pa[it];
        *(uint4*)&Bs[r * 36 + w4] = pb[it];
    }
    __syncthreads();

    const int nC = K >> 6;            // K-chunk = 64 halves
    for (int c = 0; c < nC; c++) {
        const unsigned soff = (c & 1) * (GSTG * 4);   // bytes
        unsigned* An = As + ((c & 1) ^ 1) * GSTG;
        unsigned* Bn = Bs + ((c & 1) ^ 1) * GSTG;

        const bool more = (c + 1 < nC);
        if (more) {
            const int k0 = (c + 1) * 64;
#pragma unroll
            for (int it = 0; it < 4; it++) {
                const int i = tid + 256 * it;
                const int r = i >> 3, c8 = (i & 7) * 8;
                pa[it] = *(const uint4*)(aP + (size_t)r * K + k0 + c8);
                pb[it] = *(const uint4*)(bP + (size_t)r * K + k0 + c8);
            }
        }

#pragma unroll
        for (int ks = 0; ks < 4; ks++) {              // k16 per step
            const unsigned ko = soff + ks * 32;       // 16 halves = 32 B
            unsigned a[2][4], bf[4][4];
            ldsm4(a[0], aAddr[0] + ko);
            ldsm4(a[1], aAddr[1] + ko);
#pragma unroll
            for (int np = 0; np < 4; np++) ldsm4(bf[np], bAddr[np] + ko);
#pragma unroll
            for (int np = 0; np < 4; np++) {
                mma16(acc[0][2 * np],     a[0], &bf[np][0]);
                mma16(acc[1][2 * np],     a[1], &bf[np][0]);
                mma16(acc[0][2 * np + 1], a[0], &bf[np][2]);
                mma16(acc[1][2 * np + 1], a[1], &bf[np][2]);
            }
        }

        if (more) {
#pragma unroll
            for (int it = 0; it < 4; it++) {
                const int i = tid + 256 * it;
                const int r = i >> 3, w4 = (i & 7) * 4;
                *(uint4*)&An[r * 36 + w4] = pa[it];
                *(uint4*)&Bn[r * 36 + w4] = pb[it];
            }
        }
        __syncthreads();
    }

    // epilogue (C frag layout identical to k8 variant)
    const int q4 = lane & 3;
    const int g8 = lane >> 2;
#pragma unroll
    for (int mt = 0; mt < 2; mt++) {
#pragma unroll
        for (int rr = 0; rr < 2; rr++) {
            const int m = row0 + wm + mt * 16 + g8 + rr * 8;
#pragma unroll
            for (int nt = 0; nt < 8; nt++) {
#pragma unroll
                for (int cc = 0; cc < 2; cc++) {
                    const int n = col0 + wn + nt * 8 + 2 * q4 + cc;
                    float v = acc[mt][nt][rr * 2 + cc] + bias[n];
                    if (mode == 0) {
                        const int sec = n >> 10;
                        const int e = n & 1023;
                        const int h = e >> 6, d = e & 63;
                        const int t = m >> 2, b = m & 3;
                        const int bh = b * NH + h;
                        if (sec == 0)  // 0.125 * log2(e)
                            g_q[(bh * T_LEN + t) * HD + d] =
                                __float2half_rn(v * 0.18033688f);
                        else if (sec == 1)
                            g_k[(bh * T_LEN + t) * HD + d] = __float2half_rn(v);
                        else  // V transposed: [bh][d][t]
                            g_v[((size_t)bh * HD + d) * T_LEN + t] =
                                __float2half_rn(v);
                    } else {
                        Cout[(size_t)m * N + n] = v;
                    }
                }
            }
        }
    }
}

// ---------------------------------------------------------------------------
// FP16 flash attention: 64-row q-tiles, 4 warps x 16 rows, register K/V
// prefetch, base-2 softmax, saturation fast path, MMA qr prologue.
// grid = (16 q-tiles, 64 heads), 128 threads. 45KB smem.
// ---------------------------------------------------------------------------
__global__ void __launch_bounds__(128)
attn_tc(const float* __restrict__ relk)
{
    extern __shared__ float sm[];
    unsigned* Qs = (unsigned*)sm;             // [64][36]w rows=t, cols=d halves
    unsigned* Ks = Qs + 64 * 36;              // [64][36]w rows=s, cols=d
    unsigned* Vs = Ks + 64 * 36;              // [64][36]w rows=d, cols=s
    unsigned* Ps = Vs + 64 * 36;              // [64][36]w rows=t, cols=s
    float* qrs   = (float*)(Ps + 64 * 36);    // [64][33] fp32
    __half* relsH = (__half*)Ps;              // overlay rows 0..47 (33..47 zero)

    const int tid  = threadIdx.x;
    const int lane = tid & 31;
    const int warp = tid >> 5;                // 0..3
    const int q4   = lane & 3;
    const int g8   = lane >> 2;               // 0..7
    const int bh   = blockIdx.y;
    const int tq0  = blockIdx.x * 64;
    const int m0   = warp * 16;

    const int lrow = lane & 7;
    const int lb3  = (lane >> 3) & 1;
    const int lb4  = lane >> 4;
    const unsigned qAddr = smem_u32(&Qs[(m0 + lrow + lb3 * 8) * 36 + lb4 * 4]);
    const unsigned pAddr = smem_u32(&Ps[(m0 + lrow + lb3 * 8) * 36 + lb4 * 4]);
    unsigned kAddr[4], vAddr[4], relAddr[3];
#pragma unroll
    for (int np = 0; np < 4; np++) {
        kAddr[np] = smem_u32(&Ks[(np * 16 + lb4 * 8 + lrow) * 36 + lb3 * 4]);
        vAddr[np] = smem_u32(&Vs[(np * 16 + lb4 * 8 + lrow) * 36 + lb3 * 4]);
    }
#pragma unroll
    for (int np = 0; np < 3; np++)
        relAddr[np] = smem_u32(&((unsigned*)relsH)[(np * 16 + lb4 * 8 + lrow) * 36 + lb3 * 4]);

    // load Q tile (64x64 halves = 512 uint4)
    {
        const uint4* qb = (const uint4*)(g_q + (size_t)(bh * T_LEN + tq0) * HD);
#pragma unroll
        for (int i = tid; i < 512; i += 128)
            *(uint4*)&Qs[(i >> 3) * 36 + (i & 7) * 4] = qb[i];
    }
    // relation keys (fp16) into Ps overlay; zero rows first
    for (int i = tid; i < 64 * 36; i += 128) Ps[i] = 0u;
    __syncthreads();
    for (int i = tid; i < NREL * 64; i += 128) {
        const int j = i >> 6, d = i & 63;
        relsH[j * 72 + d] = __float2half_rn(relk[j * EMB + d]);
    }
    __syncthreads();

    // qr[r][j] = q[r] . rel[j] via MMA (j in 0..47, keep j<33)
    {
        float sq[6][4];
#pragma unroll
        for (int nt = 0; nt < 6; nt++)
#pragma unroll
            for (int f = 0; f < 4; f++) sq[nt][f] = 0.0f;
#pragma unroll
        for (int ks = 0; ks < 4; ks++) {
            const unsigned ko = ks * 32;
            unsigned a[4];
            ldsm4(a, qAddr + ko);
#pragma unroll
            for (int np = 0; np < 3; np++) {
                unsigned bf[4];
                ldsm4(bf, relAddr[np] + ko);
                mma16(sq[2 * np],     a, &bf[0]);
                mma16(sq[2 * np + 1], a, &bf[2]);
            }
        }
#pragma unroll
        for (int rid = 0; rid < 2; rid++) {
            const int rloc = m0 + rid * 8 + g8;
#pragma unroll
            for (int nt = 0; nt < 6; nt++)
#pragma unroll
                for (int cc = 0; cc < 2; cc++) {
                    const int j = nt * 8 + 2 * q4 + cc;
                    if (j < NREL) qrs[rloc * NREL + j] = sq[nt][rid * 2 + cc];
                }
        }
    }

    const __half* kbase = g_k + (size_t)bh * T_LEN * HD;   // [t][d]
    const __half* vbase = g_v + (size_t)bh * HD * T_LEN;   // [d][t]

    // prefetch tile 0 (512 uint4 per matrix, 4 per thread)
    uint4 pk[4], pv[4];
#pragma unroll
    for (int it = 0; it < 4; it++) {
        const int i = tid + 128 * it;
        const int r = i >> 3, c8 = (i & 7) * 8;
        pk[it] = *(const uint4*)(kbase + (size_t)r * HD + c8);
        pv[it] = *(const uint4*)(vbase + (size_t)r * T_LEN + c8);
    }

    float o[8][4];
#pragma unroll
    for (int nt = 0; nt < 8; nt++)
#pragma unroll
        for (int f = 0; f < 4; f++) o[nt][f] = 0.0f;
    float mrow[2] = {-1e30f, -1e30f};
    float lrw[2]  = {0.0f, 0.0f};

    __syncthreads();   // qr writes visible; rel overlay consumption complete

    for (int kt = 0; kt < 16; kt++) {
        const int s0 = kt * 64;

        // store prefetched tile: Ks rows=s cols=d; Vs rows=d cols=s
#pragma unroll
        for (int it = 0; it < 4; it++) {
            const int i = tid + 128 * it;
            const int r = i >> 3, w4 = (i & 7) * 4;
            *(uint4*)&Ks[r * 36 + w4] = pk[it];
            *(uint4*)&Vs[r * 36 + w4] = pv[it];
        }
        __syncthreads();

        // prefetch next tile
        if (kt + 1 < 16) {
            const __half* kb = kbase + (size_t)(s0 + 64) * HD;
#pragma unroll
            for (int it = 0; it < 4; it++) {
                const int i = tid + 128 * it;
                const int r = i >> 3, c8 = (i & 7) * 8;
                pk[it] = *(const uint4*)(kb + (size_t)r * HD + c8);
                pv[it] = *(const uint4*)(vbase + (size_t)r * T_LEN + s0 + 64 + c8);
            }
        }

        // S = Q @ K^T  (16 rows x 64 cols per warp), 4 k16 steps
        float s[8][4];
#pragma unroll
        for (int nt = 0; nt < 8; nt++)
#pragma unroll
            for (int f = 0; f < 4; f++) s[nt][f] = 0.0f;

#pragma unroll
        for (int ks = 0; ks < 4; ks++) {
            const unsigned ko = ks * 32;
            unsigned a[4];
            ldsm4(a, qAddr + ko);
#pragma unroll
            for (int np = 0; np < 4; np++) {
                unsigned bf[4];
                ldsm4(bf, kAddr[np] + ko);
                mma16(s[2 * np],     a, &bf[0]);
                mma16(s[2 * np + 1], a, &bf[2]);
            }
        }

        // bias + online softmax, base-2 (2 rows/lane; 4 lanes/row: xor 1,2)
#pragma unroll
        for (int rid = 0; rid < 2; rid++) {
            const int rloc = m0 + rid * 8 + g8;
            const int rg = tq0 + rloc;
            const float* qr = &qrs[rloc * NREL];
            float vals[16];
            float mx = -1e30f;
            if (s0 - rg >= 16) {               // whole tile right-saturated
                const float b32 = qr[32];
#pragma unroll
                for (int nt = 0; nt < 8; nt++)
#pragma unroll
                    for (int cc = 0; cc < 2; cc++) {
                        float v = s[nt][rid * 2 + cc] + b32;
                        vals[nt * 2 + cc] = v;
                        mx = fmaxf(mx, v);
                    }
            } else if (rg - s0 >= 79) {        // whole tile left-saturated
                const float b0 = qr[0];
#pragma unroll
                for (int nt = 0; nt < 8; nt++)
#pragma unroll
                    for (int cc = 0; cc < 2; cc++) {
                        float v = s[nt][rid * 2 + cc] + b0;
                        vals[nt * 2 + cc] = v;
                        mx = fmaxf(mx, v);
                    }
            } else {
#pragma unroll
                for (int nt = 0; nt < 8; nt++)
#pragma unroll
                    for (int cc = 0; cc < 2; cc++) {
                        const int sg = s0 + nt * 8 + 2 * q4 + cc;
                        int delta = min(max(sg - rg, -16), 16) + 16;
                        float v = s[nt][rid * 2 + cc] + qr[delta];
                        vals[nt * 2 + cc] = v;
                        mx = fmaxf(mx, v);
                    }
            }
            mx = fmaxf(mx, __shfl_xor_sync(0xffffffffu, mx, 1));
            mx = fmaxf(mx, __shfl_xor_sync(0xffffffffu, mx, 2));
            const float mnew = fmaxf(mrow[rid], mx);
            const float alpha = ex2(mrow[rid] - mnew);
            float rs = 0.0f;
#pragma unroll
            for (int j = 0; j < 16; j++) {
                vals[j] = ex2(vals[j] - mnew);
                rs += vals[j];
            }
            rs += __shfl_xor_sync(0xffffffffu, rs, 1);
            rs += __shfl_xor_sync(0xffffffffu, rs, 2);
            lrw[rid] = lrw[rid] * alpha + rs;
            mrow[rid] = mnew;
#pragma unroll
            for (int nt = 0; nt < 8; nt++) {
                o[nt][rid * 2]     *= alpha;
                o[nt][rid * 2 + 1] *= alpha;
            }
            // stage P (fp16, half2 per frag-pair)
            __half* PsH = (__half*)Ps;
#pragma unroll
            for (int nt = 0; nt < 8; nt++) {
                const int cpos = nt * 8 + 2 * q4;
                *(__half2*)&PsH[rloc * 72 + cpos] =
                    __floats2half2_rn(vals[nt * 2], vals[nt * 2 + 1]);
            }
        }
        __syncwarp();   // P produced/consumed within this warp only

        // O += P @ V  (Vs rows=d(n), cols=s(k)), 4 k16 steps
#pragma unroll
        for (int ks = 0; ks < 4; ks++) {
            const unsigned ko = ks * 32;
            unsigned a[4];
            ldsm4(a, pAddr + ko);
#pragma unroll
            for (int np = 0; np < 4; np++) {
                unsigned vf[4];
                ldsm4(vf, vAddr[np] + ko);
                mma16(o[2 * np],     a, &vf[0]);
                mma16(o[2 * np + 1], a, &vf[2]);
            }
        }
        __syncthreads();   // done reading Ks/Vs; safe to overwrite next iter
    }

    // write attn (fp16) in [t][b][e] layout
    const int b = bh >> 4, h = bh & 15;
#pragma unroll
    for (int rid = 0; rid < 2; rid++) {
        const int t = tq0 + m0 + rid * 8 + g8;
        const float inv = 1.0f / lrw[rid];
#pragma unroll
        for (int nt = 0; nt < 8; nt++) {
            const int d = nt * 8 + 2 * q4;
            *(__half2*)&g_attn[(size_t)(t * BATCH + b) * EMB + h * HD + d] =
                __floats2half2_rn(o[nt][rid * 2] * inv, o[nt][rid * 2 + 1] * inv);
        }
    }
}

// ---------------------------------------------------------------------------
extern "C" void kernel_launch(void* const* d_in, const int* in_sizes, int n_in,
                              void* d_out, int out_size)
{
    (void)in_sizes; (void)n_in; (void)out_size;
    const float* query = (const float*)d_in[0];   // [T,B,E]
    const float* w_in  = (const float*)d_in[1];   // [3E,E]
    const float* b_in  = (const float*)d_in[2];   // [3E]
    const float* relk  = (const float*)d_in[3];   // [33,E]
    const float* w_out = (const float*)d_in[4];   // [E,E]
    const float* b_out = (const float*)d_in[5];   // [E]
    float* out = (float*)d_out;                   // [T,B,E]

    __half *qin, *win, *wout, *attn_ptr;
    cudaGetSymbolAddress((void**)&qin,  g_qin);
    cudaGetSymbolAddress((void**)&win,  g_win);
    cudaGetSymbolAddress((void**)&wout, g_wout);
    cudaGetSymbolAddress((void**)&attn_ptr, g_attn);

    // 0) one-time fp32 -> fp16 pre-conversion
    cvt_f16<<<4096, 256>>>(query, qin, 4096 * 1024 / 4);
    cvt_f16<<<3072, 256>>>(w_in,  win, 3072 * 1024 / 4);
    cvt_f16<<<1024, 256>>>(w_out, wout, 1024 * 1024 / 4);

    const size_t gemm_smem = (size_t)4 * GSTG * sizeof(unsigned);  // 73728 B
    cudaFuncSetAttribute(gemm_tc,
                         cudaFuncAttributeMaxDynamicSharedMemorySize,
                         (int)gemm_smem);

    // 1) fused QKV projection -> fp16 head-major q/k/v (V transposed)
    gemm_tc<<<dim3(24, 32), 256, gemm_smem>>>(
        qin, win, b_in, nullptr, 4096, 3072, 1024, 0);

    // 2) flash attention with relative bias
    const size_t attn_smem =
        (size_t)(4 * 64 * 36 + 64 * NREL) * sizeof(unsigned);  // 45312 B
    cudaFuncSetAttribute(attn_tc,
                         cudaFuncAttributeMaxDynamicSharedMemorySize,
                         (int)attn_smem);
    attn_tc<<<dim3(16, 64), 128, attn_smem>>>(relk);

    // 3) output projection (writes fp32 final output)
    gemm_tc<<<dim3(8, 32), 256, gemm_smem>>>(
        attn_ptr, wout, b_out, out, 4096, 1024, 1024, 1);
}

// round 13
// speedup vs baseline: 1.9780x; 1.1071x over previous
#include <cuda_runtime.h>
#include <cuda_fp16.h>

#define T_LEN 1024
#define BATCH 4
#define EMB   1024
#define NH    16
#define HD    64
#define BH    (BATCH*NH)   // 64
#define NREL  33           // 2L+1

// Scratch (static device arrays: allocation-free per harness rules)
__device__ __half g_q[BH * T_LEN * HD];        // fp16, pre-scaled by 0.125*log2e
__device__ __half g_k[BH * T_LEN * HD];        // fp16
__device__ __half g_v[BH * HD * T_LEN];        // fp16, TRANSPOSED [bh][d][t]
__device__ __half g_attn[T_LEN * BATCH * EMB]; // fp16, [t*4+b][e]
__device__ __half g_qin[4096 * 1024];          // fp16(query)
__device__ __half g_win[3072 * 1024];          // fp16(w_in)
__device__ __half g_wout[1024 * 1024];         // fp16(w_out)

__device__ __forceinline__ float ex2(float x) {
    float y;
    asm("ex2.approx.ftz.f32 %0, %1;" : "=f"(y) : "f"(x));
    return y;
}

// m16n8k16 fp16 -> fp32. c aliases d.
__device__ __forceinline__ void mma16(float* c, const unsigned* a, const unsigned* b) {
    asm volatile(
        "mma.sync.aligned.m16n8k16.row.col.f32.f16.f16.f32 "
        "{%0,%1,%2,%3}, {%4,%5,%6,%7}, {%8,%9}, {%0,%1,%2,%3};\n"
        : "+f"(c[0]), "+f"(c[1]), "+f"(c[2]), "+f"(c[3])
        : "r"(a[0]), "r"(a[1]), "r"(a[2]), "r"(a[3]), "r"(b[0]), "r"(b[1]));
}

__device__ __forceinline__ unsigned smem_u32(const void* p) {
    return (unsigned)__cvta_generic_to_shared(p);
}

__device__ __forceinline__ void ldsm4(unsigned* d, unsigned addr) {
    asm volatile(
        "ldmatrix.sync.aligned.m8n8.x4.shared.b16 {%0,%1,%2,%3}, [%4];"
        : "=r"(d[0]), "=r"(d[1]), "=r"(d[2]), "=r"(d[3]) : "r"(addr));
}

__device__ __forceinline__ void cpa16(unsigned dst, const void* src) {
    asm volatile("cp.async.cg.shared.global [%0], [%1], 16;"
                 :: "r"(dst), "l"(src));
}

// ---------------------------------------------------------------------------
// Fused fp32 -> fp16(rn) pre-conversion for query, w_in, w_out (one launch).
// i indexes float4 units: [0,1048576) query, [.., 1835008) w_in, rest w_out.
// ---------------------------------------------------------------------------
__global__ void __launch_bounds__(256)
cvt_all(const float* __restrict__ q, const float* __restrict__ wi,
        const float* __restrict__ wo)
{
    const int i = blockIdx.x * 256 + threadIdx.x;
    const float* src;
    __half* dst;
    int off;
    if (i < 1048576)      { src = q;  dst = g_qin;  off = i; }
    else if (i < 1835008) { src = wi; dst = g_win;  off = i - 1048576; }
    else                  { src = wo; dst = g_wout; off = i - 1835008; }
    float4 v = ((const float4*)src)[off];
    ((__half2*)dst)[2 * off]     = __floats2half2_rn(v.x, v.y);
    ((__half2*)dst)[2 * off + 1] = __floats2half2_rn(v.z, v.w);
}

// ---------------------------------------------------------------------------
// FP16 TC GEMM: C[M,N] = A[M,K] * B[N,K]^T + bias[N].
// Block 128x128, K-chunk 64 halves, 8 warps (32m x 64n tiles), cp.async
// 2-stage pipeline, LDSM fragments, 2 CTAs/SM. Row stride 36 words.
// mode 0: scatter q/k/v fp16 (q scaled by 0.125*log2e, V transposed).
// mode 1: write fp32 Cout.
// ---------------------------------------------------------------------------
#define GSTG (128 * 36)          // words per matrix per stage
#define GSTGB (GSTG * 4)

__global__ void __launch_bounds__(256, 2)
gemm_tc(const __half* __restrict__ A, const __half* __restrict__ B,
        const float* __restrict__ bias, float* __restrict__ Cout,
        int M, int N, int K, int mode)
{
    extern __shared__ unsigned sh[];
    unsigned* As = sh;               // [2][128*36] words
    unsigned* Bs = sh + 2 * GSTG;

    const int tid  = threadIdx.x;
    const int lane = tid & 31;
    const int warp = tid >> 5;
    const int wm   = (warp & 3) * 32;
    const int wn   = (warp >> 2) * 64;
    const int row0 = blockIdx.y * 128;
    const int col0 = blockIdx.x * 128;

    const int lrow = lane & 7;
    const int lb3  = (lane >> 3) & 1;
    const int lb4  = lane >> 4;
    unsigned aAddr[2], bAddr[4];
#pragma unroll
    for (int mt = 0; mt < 2; mt++)
        aAddr[mt] = smem_u32(&As[(wm + mt * 16 + lrow + lb3 * 8) * 36 + lb4 * 4]);
#pragma unroll
    for (int np = 0; np < 4; np++)
        bAddr[np] = smem_u32(&Bs[(wn + np * 16 + lb4 * 8 + lrow) * 36 + lb3 * 4]);

    const unsigned aSm = smem_u32(As);
    const unsigned bSm = smem_u32(Bs);

    float acc[2][8][4];
#pragma unroll
    for (int mt = 0; mt < 2; mt++)
#pragma unroll
        for (int nt = 0; nt < 8; nt++)
#pragma unroll
            for (int f = 0; f < 4; f++) acc[mt][nt][f] = 0.0f;

    const __half* aP = A + (size_t)row0 * K;
    const __half* bP = B + (size_t)col0 * K;

    // one chunk = 128 rows x 64 halves = 1024 16B segments per matrix;
    // 4 per thread: i = tid + 256*it, r = i>>3, seg = i&7
    auto issue = [&](int k0, int st) {
        const unsigned aDst = aSm + (unsigned)st * GSTGB;
        const unsigned bDst = bSm + (unsigned)st * GSTGB;
#pragma unroll
        for (int it = 0; it < 4; it++) {
            const int i = tid + 256 * it;
            const int r = i >> 3, seg = i & 7;
            const unsigned doff = (unsigned)(r * 36 + seg * 4) * 4;
            cpa16(aDst + doff, aP + (size_t)r * K + k0 + seg * 8);
            cpa16(bDst + doff, bP + (size_t)r * K + k0 + seg * 8);
        }
        asm volatile("cp.async.commit_group;");
    };

    const int nC = K >> 6;
    issue(0, 0);

    for (int c = 0; c < nC; c++) {
        const int st = c & 1;
        const unsigned soff = (unsigned)st * GSTGB;

        if (c + 1 < nC) {
            issue((c + 1) * 64, st ^ 1);
            asm volatile("cp.async.wait_group 1;");
        } else {
            asm volatile("cp.async.wait_group 0;");
        }
        __syncthreads();     // chunk c resident for all warps

#pragma unroll
        for (int ks = 0; ks < 4; ks++) {              // k16 per step
            const unsigned ko = soff + ks * 32;       // 16 halves = 32 B
            unsigned a[2][4], bf[4][4];
            ldsm4(a[0], aAddr[0] + ko);
            ldsm4(a[1], aAddr[1] + ko);
#pragma unroll
            for (int np = 0; np < 4; np++) ldsm4(bf[np], bAddr[np] + ko);
#pragma unroll
            for (int np = 0; np < 4; np++) {
                mma16(acc[0][2 * np],     a[0], &bf[np][0]);
                mma16(acc[1][2 * np],     a[1], &bf[np][0]);
                mma16(acc[0][2 * np + 1], a[0], &bf[np][2]);
                mma16(acc[1][2 * np + 1], a[1], &bf[np][2]);
            }
        }
        __syncthreads();     // all warps done with stage st before refill
    }

    // epilogue
    const int q4 = lane & 3;
    const int g8 = lane >> 2;
#pragma unroll
    for (int mt = 0; mt < 2; mt++) {
#pragma unroll
        for (int rr = 0; rr < 2; rr++) {
            const int m = row0 + wm + mt * 16 + g8 + rr * 8;
#pragma unroll
            for (int nt = 0; nt < 8; nt++) {
#pragma unroll
                for (int cc = 0; cc < 2; cc++) {
                    const int n = col0 + wn + nt * 8 + 2 * q4 + cc;
                    float v = acc[mt][nt][rr * 2 + cc] + bias[n];
                    if (mode == 0) {
                        const int sec = n >> 10;
                        const int e = n & 1023;
                        const int h = e >> 6, d = e & 63;
                        const int t = m >> 2, b = m & 3;
                        const int bh = b * NH + h;
                        if (sec == 0)  // 0.125 * log2(e)
                            g_q[(bh * T_LEN + t) * HD + d] =
                                __float2half_rn(v * 0.18033688f);
                        else if (sec == 1)
                            g_k[(bh * T_LEN + t) * HD + d] = __float2half_rn(v);
                        else  // V transposed: [bh][d][t]
                            g_v[((size_t)bh * HD + d) * T_LEN + t] =
                                __float2half_rn(v);
                    } else {
                        Cout[(size_t)m * N + n] = v;
                    }
                }
            }
        }
    }
}

// ---------------------------------------------------------------------------
// FP16 flash attention: 64-row q-tiles, 4 warps x 16 rows, register K/V
// prefetch, base-2 softmax, saturation fast path, MMA qr prologue.
// P fed to PV MMA DIRECTLY FROM REGISTERS (A-fragment layout owned in-lane)
// — no smem staging, no syncwarp. grid = (16 q-tiles, 64 heads), 128 thr.
// ---------------------------------------------------------------------------
__global__ void __launch_bounds__(128)
attn_tc(const float* __restrict__ relk)
{
    extern __shared__ float sm[];
    unsigned* Qs = (unsigned*)sm;             // [64][36]w rows=t, cols=d halves
    unsigned* Ks = Qs + 64 * 36;              // [64][36]w rows=s, cols=d
    unsigned* Vs = Ks + 64 * 36;              // [64][36]w rows=d, cols=s
    unsigned* Rs = Vs + 64 * 36;              // [64][36]w rel overlay (rows>=33 zero)
    float* qrs   = (float*)(Rs + 64 * 36);    // [64][33] fp32

    const int tid  = threadIdx.x;
    const int lane = tid & 31;
    const int warp = tid >> 5;                // 0..3
    const int q4   = lane & 3;
    const int g8   = lane >> 2;               // 0..7
    const int bh   = blockIdx.y;
    const int tq0  = blockIdx.x * 64;
    const int m0   = warp * 16;

    const int lrow = lane & 7;
    const int lb3  = (lane >> 3) & 1;
    const int lb4  = lane >> 4;
    const unsigned qAddr = smem_u32(&Qs[(m0 + lrow + lb3 * 8) * 36 + lb4 * 4]);
    unsigned kAddr[4], vAddr[4], relAddr[3];
#pragma unroll
    for (int np = 0; np < 4; np++) {
        kAddr[np] = smem_u32(&Ks[(np * 16 + lb4 * 8 + lrow) * 36 + lb3 * 4]);
        vAddr[np] = smem_u32(&Vs[(np * 16 + lb4 * 8 + lrow) * 36 + lb3 * 4]);
    }
#pragma unroll
    for (int np = 0; np < 3; np++)
        relAddr[np] = smem_u32(&Rs[(np * 16 + lb4 * 8 + lrow) * 36 + lb3 * 4]);

    // load Q tile (64x64 halves = 512 uint4)
    {
        const uint4* qb = (const uint4*)(g_q + (size_t)(bh * T_LEN + tq0) * HD);
#pragma unroll
        for (int i = tid; i < 512; i += 128)
            *(uint4*)&Qs[(i >> 3) * 36 + (i & 7) * 4] = qb[i];
    }
    // relation keys (fp16) into Rs; zero first (rows 33..63 stay zero)
    for (int i = tid; i < 64 * 36; i += 128) Rs[i] = 0u;
    __syncthreads();
    {
        __half* relsH = (__half*)Rs;
        for (int i = tid; i < NREL * 64; i += 128) {
            const int j = i >> 6, d = i & 63;
            relsH[j * 72 + d] = __float2half_rn(relk[j * EMB + d]);
        }
    }
    __syncthreads();

    // qr[r][j] = q[r] . rel[j] via MMA (j in 0..47, keep j<33)
    {
        float sq[6][4];
#pragma unroll
        for (int nt = 0; nt < 6; nt++)
#pragma unroll
            for (int f = 0; f < 4; f++) sq[nt][f] = 0.0f;
#pragma unroll
        for (int ks = 0; ks < 4; ks++) {
            const unsigned ko = ks * 32;
            unsigned a[4];
            ldsm4(a, qAddr + ko);
#pragma unroll
            for (int np = 0; np < 3; np++) {
                unsigned bf[4];
                ldsm4(bf, relAddr[np] + ko);
                mma16(sq[2 * np],     a, &bf[0]);
                mma16(sq[2 * np + 1], a, &bf[2]);
            }
        }
#pragma unroll
        for (int rid = 0; rid < 2; rid++) {
            const int rloc = m0 + rid * 8 + g8;
#pragma unroll
            for (int nt = 0; nt < 6; nt++)
#pragma unroll
                for (int cc = 0; cc < 2; cc++) {
                    const int j = nt * 8 + 2 * q4 + cc;
                    if (j < NREL) qrs[rloc * NREL + j] = sq[nt][rid * 2 + cc];
                }
        }
    }

    const __half* kbase = g_k + (size_t)bh * T_LEN * HD;   // [t][d]
    const __half* vbase = g_v + (size_t)bh * HD * T_LEN;   // [d][t]

    // prefetch tile 0 (512 uint4 per matrix, 4 per thread)
    uint4 pk[4], pv[4];
#pragma unroll
    for (int it = 0; it < 4; it++) {
        const int i = tid + 128 * it;
        const int r = i >> 3, c8 = (i & 7) * 8;
        pk[it] = *(const uint4*)(kbase + (size_t)r * HD + c8);
        pv[it] = *(const uint4*)(vbase + (size_t)r * T_LEN + c8);
    }

    float o[8][4];
#pragma unroll
    for (int nt = 0; nt < 8; nt++)
#pragma unroll
        for (int f = 0; f < 4; f++) o[nt][f] = 0.0f;
    float mrow[2] = {-1e30f, -1e30f};
    float lrw[2]  = {0.0f, 0.0f};

    __syncthreads();   // qr writes visible

    for (int kt = 0; kt < 16; kt++) {
        const int s0 = kt * 64;

        // store prefetched tile: Ks rows=s cols=d; Vs rows=d cols=s
#pragma unroll
        for (int it = 0; it < 4; it++) {
            const int i = tid + 128 * it;
            const int r = i >> 3, w4 = (i & 7) * 4;
            *(uint4*)&Ks[r * 36 + w4] = pk[it];
            *(uint4*)&Vs[r * 36 + w4] = pv[it];
        }
        __syncthreads();

        // prefetch next tile
        if (kt + 1 < 16) {
            const __half* kb = kbase + (size_t)(s0 + 64) * HD;
#pragma unroll
            for (int it = 0; it < 4; it++) {
                const int i = tid + 128 * it;
                const int r = i >> 3, c8 = (i & 7) * 8;
                pk[it] = *(const uint4*)(kb + (size_t)r * HD + c8);
                pv[it] = *(const uint4*)(vbase + (size_t)r * T_LEN + s0 + 64 + c8);
            }
        }

        // S = Q @ K^T  (16 rows x 64 cols per warp), 4 k16 steps
        float s[8][4];
#pragma unroll
        for (int nt = 0; nt < 8; nt++)
#pragma unroll
            for (int f = 0; f < 4; f++) s[nt][f] = 0.0f;

#pragma unroll
        for (int ks = 0; ks < 4; ks++) {
            const unsigned ko = ks * 32;
            unsigned a[4];
            ldsm4(a, qAddr + ko);
#pragma unroll
            for (int np = 0; np < 4; np++) {
                unsigned bf[4];
                ldsm4(bf, kAddr[np] + ko);
                mma16(s[2 * np],     a, &bf[0]);
                mma16(s[2 * np + 1], a, &bf[2]);
            }
        }

        // bias + online softmax, base-2; pack P directly into A-fragments
        unsigned ph[2][8];    // ph[rid][j] = half2(P[.., 2j], P[.., 2j+1])
#pragma unroll
        for (int rid = 0; rid < 2; rid++) {
            const int rloc = m0 + rid * 8 + g8;
            const int rg = tq0 + rloc;
            const float* qr = &qrs[rloc * NREL];
            float vals[16];
            float mx = -1e30f;
            if (s0 - rg >= 16) {               // whole tile right-saturated
                const float b32 = qr[32];
#pragma unroll
                for (int nt = 0; nt < 8; nt++)
#pragma unroll
                    for (int cc = 0; cc < 2; cc++) {
                        float v = s[nt][rid * 2 + cc] + b32;
                        vals[nt * 2 + cc] = v;
                        mx = fmaxf(mx, v);
                    }
            } else if (rg - s0 >= 79) {        // whole tile left-saturated
                const float b0 = qr[0];
#pragma unroll
                for (int nt = 0; nt < 8; nt++)
#pragma unroll
                    for (int cc = 0; cc < 2; cc++) {
                        float v = s[nt][rid * 2 + cc] + b0;
                        vals[nt * 2 + cc] = v;
                        mx = fmaxf(mx, v);
                    }
            } else {
#pragma unroll
                for (int nt = 0; nt < 8; nt++)
#pragma unroll
                    for (int cc = 0; cc < 2; cc++) {
                        const int sg = s0 + nt * 8 + 2 * q4 + cc;
                        int delta = min(max(sg - rg, -16), 16) + 16;
                        float v = s[nt][rid * 2 + cc] + qr[delta];
                        vals[nt * 2 + cc] = v;
                        mx = fmaxf(mx, v);
                    }
            }
            mx = fmaxf(mx, __shfl_xor_sync(0xffffffffu, mx, 1));
            mx = fmaxf(mx, __shfl_xor_sync(0xffffffffu, mx, 2));
            const float mnew = fmaxf(mrow[rid], mx);
            const float alpha = ex2(mrow[rid] - mnew);
            float rs = 0.0f;
#pragma unroll
            for (int j = 0; j < 16; j++) {
                vals[j] = ex2(vals[j] - mnew);
                rs += vals[j];
            }
            rs += __shfl_xor_sync(0xffffffffu, rs, 1);
            rs += __shfl_xor_sync(0xffffffffu, rs, 2);
            lrw[rid] = lrw[rid] * alpha + rs;
            mrow[rid] = mnew;
#pragma unroll
            for (int nt = 0; nt < 8; nt++) {
                o[nt][rid * 2]     *= alpha;
                o[nt][rid * 2 + 1] *= alpha;
            }
#pragma unroll
            for (int j = 0; j < 8; j++) {
                __half2 h = __floats2half2_rn(vals[2 * j], vals[2 * j + 1]);
                ph[rid][j] = *(unsigned*)&h;
            }
        }

        // O += P @ V : P A-fragments straight from ph registers
#pragma unroll
        for (int ks = 0; ks < 4; ks++) {
            unsigned a[4];
            a[0] = ph[0][2 * ks];
            a[1] = ph[1][2 * ks];
            a[2] = ph[0][2 * ks + 1];
            a[3] = ph[1][2 * ks + 1];
            const unsigned ko = ks * 32;
#pragma unroll
            for (int np = 0; np < 4; np++) {
                unsigned vf[4];
                ldsm4(vf, vAddr[np] + ko);
                mma16(o[2 * np],     a, &vf[0]);
                mma16(o[2 * np + 1], a, &vf[2]);
            }
        }
        __syncthreads();   // done reading Ks/Vs; safe to overwrite next iter
    }

    // write attn (fp16) in [t][b][e] layout
    const int b = bh >> 4, h = bh & 15;
#pragma unroll
    for (int rid = 0; rid < 2; rid++) {
        const int t = tq0 + m0 + rid * 8 + g8;
        const float inv = 1.0f / lrw[rid];
#pragma unroll
        for (int nt = 0; nt < 8; nt++) {
            const int d = nt * 8 + 2 * q4;
            *(__half2*)&g_attn[(size_t)(t * BATCH + b) * EMB + h * HD + d] =
                __floats2half2_rn(o[nt][rid * 2] * inv, o[nt][rid * 2 + 1] * inv);
        }
    }
}

// ---------------------------------------------------------------------------
extern "C" void kernel_launch(void* const* d_in, const int* in_sizes, int n_in,
                              void* d_out, int out_size)
{
    (void)in_sizes; (void)n_in; (void)out_size;
    const float* query = (const float*)d_in[0];   // [T,B,E]
    const float* w_in  = (const float*)d_in[1];   // [3E,E]
    const float* b_in  = (const float*)d_in[2];   // [3E]
    const float* relk  = (const float*)d_in[3];   // [33,E]
    const float* w_out = (const float*)d_in[4];   // [E,E]
    const float* b_out = (const float*)d_in[5];   // [E]
    float* out = (float*)d_out;                   // [T,B,E]

    __half *qin, *win, *wout, *attn_ptr;
    cudaGetSymbolAddress((void**)&qin,  g_qin);
    cudaGetSymbolAddress((void**)&win,  g_win);
    cudaGetSymbolAddress((void**)&wout, g_wout);
    cudaGetSymbolAddress((void**)&attn_ptr, g_attn);

    // 0) one-time fp32 -> fp16 pre-conversion (single fused launch)
    cvt_all<<<8192, 256>>>(query, w_in, w_out);

    const size_t gemm_smem = (size_t)4 * GSTG * sizeof(unsigned);  // 73728 B
    cudaFuncSetAttribute(gemm_tc,
                         cudaFuncAttributeMaxDynamicSharedMemorySize,
                         (int)gemm_smem);

    // 1) fused QKV projection -> fp16 head-major q/k/v (V transposed)
    gemm_tc<<<dim3(24, 32), 256, gemm_smem>>>(
        qin, win, b_in, nullptr, 4096, 3072, 1024, 0);

    // 2) flash attention with relative bias
    const size_t attn_smem =
        (size_t)(4 * 64 * 36 + 64 * NREL) * sizeof(unsigned);  // 45312 B
    cudaFuncSetAttribute(attn_tc,
                         cudaFuncAttributeMaxDynamicSharedMemorySize,
                         (int)attn_smem);
    attn_tc<<<dim3(16, 64), 128, attn_smem>>>(relk);

    // 3) output projection (writes fp32 final output)
    gemm_tc<<<dim3(8, 32), 256, gemm_smem>>>(
        attn_ptr, wout, b_out, out, 4096, 1024, 1024, 1);
}

// round 14
// speedup vs baseline: 2.0864x; 1.0548x over previous
#include <cuda_runtime.h>
#include <cuda_fp16.h>

#define T_LEN 1024
#define BATCH 4
#define EMB   1024
#define NH    16
#define HD    64
#define BH    (BATCH*NH)   // 64
#define NREL  33           // 2L+1

// Scratch (static device arrays: allocation-free per harness rules)
__device__ __half g_q[BH * T_LEN * HD];        // fp16, pre-scaled by 0.125*log2e
__device__ __half g_k[BH * T_LEN * HD];        // fp16
__device__ __half g_v[BH * HD * T_LEN];        // fp16, TRANSPOSED [bh][d][t]
__device__ __half g_attn[T_LEN * BATCH * EMB]; // fp16, [t*4+b][e]
__device__ __half g_qin[4096 * 1024];          // fp16(query)
__device__ __half g_win[3072 * 1024];          // fp16(w_in)
__device__ __half g_wout[1024 * 1024];         // fp16(w_out)

__device__ __forceinline__ float ex2(float x) {
    float y;
    asm("ex2.approx.ftz.f32 %0, %1;" : "=f"(y) : "f"(x));
    return y;
}

// m16n8k16 fp16 -> fp32. c aliases d.
__device__ __forceinline__ void mma16(float* c, const unsigned* a, const unsigned* b) {
    asm volatile(
        "mma.sync.aligned.m16n8k16.row.col.f32.f16.f16.f32 "
        "{%0,%1,%2,%3}, {%4,%5,%6,%7}, {%8,%9}, {%0,%1,%2,%3};\n"
        : "+f"(c[0]), "+f"(c[1]), "+f"(c[2]), "+f"(c[3])
        : "r"(a[0]), "r"(a[1]), "r"(a[2]), "r"(a[3]), "r"(b[0]), "r"(b[1]));
}

__device__ __forceinline__ unsigned smem_u32(const void* p) {
    return (unsigned)__cvta_generic_to_shared(p);
}

__device__ __forceinline__ void ldsm4(unsigned* d, unsigned addr) {
    asm volatile(
        "ldmatrix.sync.aligned.m8n8.x4.shared.b16 {%0,%1,%2,%3}, [%4];"
        : "=r"(d[0]), "=r"(d[1]), "=r"(d[2]), "=r"(d[3]) : "r"(addr));
}

__device__ __forceinline__ void cpa16(unsigned dst, const void* src) {
    asm volatile("cp.async.cg.shared.global [%0], [%1], 16;"
                 :: "r"(dst), "l"(src));
}

// ---------------------------------------------------------------------------
// Fused fp32 -> fp16(rn) pre-conversion for query, w_in, w_out (one launch).
// ---------------------------------------------------------------------------
__global__ void __launch_bounds__(256)
cvt_all(const float* __restrict__ q, const float* __restrict__ wi,
        const float* __restrict__ wo)
{
    const int i = blockIdx.x * 256 + threadIdx.x;
    const float* src;
    __half* dst;
    int off;
    if (i < 1048576)      { src = q;  dst = g_qin;  off = i; }
    else if (i < 1835008) { src = wi; dst = g_win;  off = i - 1048576; }
    else                  { src = wo; dst = g_wout; off = i - 1835008; }
    float4 v = ((const float4*)src)[off];
    ((__half2*)dst)[2 * off]     = __floats2half2_rn(v.x, v.y);
    ((__half2*)dst)[2 * off + 1] = __floats2half2_rn(v.z, v.w);
}

// ---------------------------------------------------------------------------
// FP16 TC GEMM: C[M,N] = A[M,K] * B[N,K]^T + bias[N].
// Block 128x128, K-chunk 64 halves, 8 warps (32m x 64n tiles), cp.async
// THREE-stage ring (ONE barrier per chunk), LDSM fragments, 2 CTAs/SM.
// mode 0: scatter q/k/v fp16 (q scaled by 0.125*log2e, V transposed).
// mode 1: write fp32 Cout.
// ---------------------------------------------------------------------------
#define GSTG (128 * 36)          // words per matrix per stage
#define GSTGB (GSTG * 4)

__global__ void __launch_bounds__(256, 2)
gemm_tc(const __half* __restrict__ A, const __half* __restrict__ B,
        const float* __restrict__ bias, float* __restrict__ Cout,
        int M, int N, int K, int mode)
{
    extern __shared__ unsigned sh[];
    unsigned* As = sh;               // [3][128*36] words
    unsigned* Bs = sh + 3 * GSTG;

    const int tid  = threadIdx.x;
    const int lane = tid & 31;
    const int warp = tid >> 5;
    const int wm   = (warp & 3) * 32;
    const int wn   = (warp >> 2) * 64;
    const int row0 = blockIdx.y * 128;
    const int col0 = blockIdx.x * 128;

    const int lrow = lane & 7;
    const int lb3  = (lane >> 3) & 1;
    const int lb4  = lane >> 4;
    unsigned aAddr[2], bAddr[4];
#pragma unroll
    for (int mt = 0; mt < 2; mt++)
        aAddr[mt] = smem_u32(&As[(wm + mt * 16 + lrow + lb3 * 8) * 36 + lb4 * 4]);
#pragma unroll
    for (int np = 0; np < 4; np++)
        bAddr[np] = smem_u32(&Bs[(wn + np * 16 + lb4 * 8 + lrow) * 36 + lb3 * 4]);

    const unsigned aSm = smem_u32(As);
    const unsigned bSm = smem_u32(Bs);

    float acc[2][8][4];
#pragma unroll
    for (int mt = 0; mt < 2; mt++)
#pragma unroll
        for (int nt = 0; nt < 8; nt++)
#pragma unroll
            for (int f = 0; f < 4; f++) acc[mt][nt][f] = 0.0f;

    const __half* aP = A + (size_t)row0 * K;
    const __half* bP = B + (size_t)col0 * K;

    // one chunk = 128 rows x 64 halves = 1024 16B segments per matrix;
    // 4 per thread: i = tid + 256*it, r = i>>3, seg = i&7
    auto issue = [&](int k0, int st) {
        const unsigned aDst = aSm + (unsigned)st * GSTGB;
        const unsigned bDst = bSm + (unsigned)st * GSTGB;
#pragma unroll
        for (int it = 0; it < 4; it++) {
            const int i = tid + 256 * it;
            const int r = i >> 3, seg = i & 7;
            const unsigned doff = (unsigned)(r * 36 + seg * 4) * 4;
            cpa16(aDst + doff, aP + (size_t)r * K + k0 + seg * 8);
            cpa16(bDst + doff, bP + (size_t)r * K + k0 + seg * 8);
        }
        asm volatile("cp.async.commit_group;");
    };

    const int nC = K >> 6;
    issue(0, 0);
    if (nC > 1) issue(64, 1);

    for (int c = 0; c < nC; c++) {
        const int st = c % 3;
        const unsigned soff = (unsigned)st * GSTGB;

        // chunk c's group completes (newest group may stay in flight)
        if (c + 1 < nC) asm volatile("cp.async.wait_group 1;");
        else            asm volatile("cp.async.wait_group 0;");
        __syncthreads();     // chunk c resident; stage (c+2)%3 fully consumed

        if (c + 2 < nC) issue((c + 2) * 64, (c + 2) % 3);

#pragma unroll
        for (int ks = 0; ks < 4; ks++) {              // k16 per step
            const unsigned ko = soff + ks * 32;       // 16 halves = 32 B
            unsigned a[2][4], bf[4][4];
            ldsm4(a[0], aAddr[0] + ko);
            ldsm4(a[1], aAddr[1] + ko);
#pragma unroll
            for (int np = 0; np < 4; np++) ldsm4(bf[np], bAddr[np] + ko);
#pragma unroll
            for (int np = 0; np < 4; np++) {
                mma16(acc[0][2 * np],     a[0], &bf[np][0]);
                mma16(acc[1][2 * np],     a[1], &bf[np][0]);
                mma16(acc[0][2 * np + 1], a[0], &bf[np][2]);
                mma16(acc[1][2 * np + 1], a[1], &bf[np][2]);
            }
        }
    }

    // epilogue
    const int q4 = lane & 3;
    const int g8 = lane >> 2;
#pragma unroll
    for (int mt = 0; mt < 2; mt++) {
#pragma unroll
        for (int rr = 0; rr < 2; rr++) {
            const int m = row0 + wm + mt * 16 + g8 + rr * 8;
#pragma unroll
            for (int nt = 0; nt < 8; nt++) {
#pragma unroll
                for (int cc = 0; cc < 2; cc++) {
                    const int n = col0 + wn + nt * 8 + 2 * q4 + cc;
                    float v = acc[mt][nt][rr * 2 + cc] + bias[n];
                    if (mode == 0) {
                        const int sec = n >> 10;
                        const int e = n & 1023;
                        const int h = e >> 6, d = e & 63;
                        const int t = m >> 2, b = m & 3;
                        const int bh = b * NH + h;
                        if (sec == 0)  // 0.125 * log2(e)
                            g_q[(bh * T_LEN + t) * HD + d] =
                                __float2half_rn(v * 0.18033688f);
                        else if (sec == 1)
                            g_k[(bh * T_LEN + t) * HD + d] = __float2half_rn(v);
                        else  // V transposed: [bh][d][t]
                            g_v[((size_t)bh * HD + d) * T_LEN + t] =
                                __float2half_rn(v);
                    } else {
                        Cout[(size_t)m * N + n] = v;
                    }
                }
            }
        }
    }
}

// ---------------------------------------------------------------------------
// FP16 flash attention: 128-row q-tiles, 8 warps x 16 rows (per-warp layout
// identical to round-13), register K/V prefetch, base-2 softmax, saturation
// fast path, MMA qr prologue, register-resident P.
// grid = (8 q-tiles, 64 heads), 256 threads. 53.8KB smem.
// ---------------------------------------------------------------------------
__global__ void __launch_bounds__(256)
attn_tc(const float* __restrict__ relk)
{
    extern __shared__ float sm[];
    unsigned* Qs = (unsigned*)sm;             // [128][36]w rows=t, cols=d halves
    unsigned* Ks = Qs + 128 * 36;             // [64][36]w  rows=s, cols=d
    unsigned* Vs = Ks + 64 * 36;              // [64][36]w  rows=d, cols=s
    float* qrs   = (float*)(Vs + 64 * 36);    // [128][33] fp32
    unsigned* Rs = Ks;                        // rel overlay on Ks (consumed first)

    const int tid  = threadIdx.x;
    const int lane = tid & 31;
    const int warp = tid >> 5;                // 0..7
    const int q4   = lane & 3;
    const int g8   = lane >> 2;               // 0..7
    const int bh   = blockIdx.y;
    const int tq0  = blockIdx.x * 128;
    const int m0   = warp * 16;

    const int lrow = lane & 7;
    const int lb3  = (lane >> 3) & 1;
    const int lb4  = lane >> 4;
    const unsigned qAddr = smem_u32(&Qs[(m0 + lrow + lb3 * 8) * 36 + lb4 * 4]);
    unsigned kAddr[4], vAddr[4], relAddr[3];
#pragma unroll
    for (int np = 0; np < 4; np++) {
        kAddr[np] = smem_u32(&Ks[(np * 16 + lb4 * 8 + lrow) * 36 + lb3 * 4]);
        vAddr[np] = smem_u32(&Vs[(np * 16 + lb4 * 8 + lrow) * 36 + lb3 * 4]);
    }
#pragma unroll
    for (int np = 0; np < 3; np++)
        relAddr[np] = smem_u32(&Rs[(np * 16 + lb4 * 8 + lrow) * 36 + lb3 * 4]);

    // load Q tile (128x64 halves = 1024 uint4)
    {
        const uint4* qb = (const uint4*)(g_q + (size_t)(bh * T_LEN + tq0) * HD);
#pragma unroll
        for (int i = tid; i < 1024; i += 256)
            *(uint4*)&Qs[(i >> 3) * 36 + (i & 7) * 4] = qb[i];
    }
    // relation keys (fp16) into Rs (= Ks region); zero first (rows 33..63 zero)
    for (int i = tid; i < 64 * 36; i += 256) Rs[i] = 0u;
    __syncthreads();
    {
        __half* relsH = (__half*)Rs;
        for (int i = tid; i < NREL * 64; i += 256) {
            const int j = i >> 6, d = i & 63;
            relsH[j * 72 + d] = __float2half_rn(relk[j * EMB + d]);
        }
    }
    __syncthreads();

    // qr[r][j] = q[r] . rel[j] via MMA (j in 0..47, keep j<33); own rows only
    {
        float sq[6][4];
#pragma unroll
        for (int nt = 0; nt < 6; nt++)
#pragma unroll
            for (int f = 0; f < 4; f++) sq[nt][f] = 0.0f;
#pragma unroll
        for (int ks = 0; ks < 4; ks++) {
            const unsigned ko = ks * 32;
            unsigned a[4];
            ldsm4(a, qAddr + ko);
#pragma unroll
            for (int np = 0; np < 3; np++) {
                unsigned bf[4];
                ldsm4(bf, relAddr[np] + ko);
                mma16(sq[2 * np],     a, &bf[0]);
                mma16(sq[2 * np + 1], a, &bf[2]);
            }
        }
#pragma unroll
        for (int rid = 0; rid < 2; rid++) {
            const int rloc = m0 + rid * 8 + g8;
#pragma unroll
            for (int nt = 0; nt < 6; nt++)
#pragma unroll
                for (int cc = 0; cc < 2; cc++) {
                    const int j = nt * 8 + 2 * q4 + cc;
                    if (j < NREL) qrs[rloc * NREL + j] = sq[nt][rid * 2 + cc];
                }
        }
    }

    const __half* kbase = g_k + (size_t)bh * T_LEN * HD;   // [t][d]
    const __half* vbase = g_v + (size_t)bh * HD * T_LEN;   // [d][t]

    // prefetch tile 0 (512 uint4 per matrix, 2 per thread)
    uint4 pk[2], pv[2];
#pragma unroll
    for (int it = 0; it < 2; it++) {
        const int i = tid + 256 * it;
        const int r = i >> 3, c8 = (i & 7) * 8;
        pk[it] = *(const uint4*)(kbase + (size_t)r * HD + c8);
        pv[it] = *(const uint4*)(vbase + (size_t)r * T_LEN + c8);
    }

    float o[8][4];
#pragma unroll
    for (int nt = 0; nt < 8; nt++)
#pragma unroll
        for (int f = 0; f < 4; f++) o[nt][f] = 0.0f;
    float mrow[2] = {-1e30f, -1e30f};
    float lrw[2]  = {0.0f, 0.0f};

    __syncthreads();   // all warps done reading Rs; qr writes complete

    for (int kt = 0; kt < 16; kt++) {
        const int s0 = kt * 64;

        // store prefetched tile: Ks rows=s cols=d; Vs rows=d cols=s
#pragma unroll
        for (int it = 0; it < 2; it++) {
            const int i = tid + 256 * it;
            const int r = i >> 3, w4 = (i & 7) * 4;
            *(uint4*)&Ks[r * 36 + w4] = pk[it];
            *(uint4*)&Vs[r * 36 + w4] = pv[it];
        }
        __syncthreads();

        // prefetch next tile
        if (kt + 1 < 16) {
            const __half* kb = kbase + (size_t)(s0 + 64) * HD;
#pragma unroll
            for (int it = 0; it < 2; it++) {
                const int i = tid + 256 * it;
                const int r = i >> 3, c8 = (i & 7) * 8;
                pk[it] = *(const uint4*)(kb + (size_t)r * HD + c8);
                pv[it] = *(const uint4*)(vbase + (size_t)r * T_LEN + s0 + 64 + c8);
            }
        }

        // S = Q @ K^T  (16 rows x 64 cols per warp), 4 k16 steps
        float s[8][4];
#pragma unroll
        for (int nt = 0; nt < 8; nt++)
#pragma unroll
            for (int f = 0; f < 4; f++) s[nt][f] = 0.0f;

#pragma unroll
        for (int ks = 0; ks < 4; ks++) {
            const unsigned ko = ks * 32;
            unsigned a[4];
            ldsm4(a, qAddr + ko);
#pragma unroll
            for (int np = 0; np < 4; np++) {
                unsigned bf[4];
                ldsm4(bf, kAddr[np] + ko);
                mma16(s[2 * np],     a, &bf[0]);
                mma16(s[2 * np + 1], a, &bf[2]);
            }
        }

        // bias + online softmax, base-2; pack P directly into A-fragments
        unsigned ph[2][8];
#pragma unroll
        for (int rid = 0; rid < 2; rid++) {
            const int rloc = m0 + rid * 8 + g8;
            const int rg = tq0 + rloc;
            const float* qr = &qrs[rloc * NREL];
            float vals[16];
            float mx = -1e30f;
            if (s0 - rg >= 16) {               // whole tile right-saturated
                const float b32 = qr[32];
#pragma unroll
                for (int nt = 0; nt < 8; nt++)
#pragma unroll
                    for (int cc = 0; cc < 2; cc++) {
                        float v = s[nt][rid * 2 + cc] + b32;
                        vals[nt * 2 + cc] = v;
                        mx = fmaxf(mx, v);
                    }
            } else if (rg - s0 >= 79) {        // whole tile left-saturated
                const float b0 = qr[0];
#pragma unroll
                for (int nt = 0; nt < 8; nt++)
#pragma unroll
                    for (int cc = 0; cc < 2; cc++) {
                        float v = s[nt][rid * 2 + cc] + b0;
                        vals[nt * 2 + cc] = v;
                        mx = fmaxf(mx, v);
                    }
            } else {
#pragma unroll
                for (int nt = 0; nt < 8; nt++)
#pragma unroll
                    for (int cc = 0; cc < 2; cc++) {
                        const int sg = s0 + nt * 8 + 2 * q4 + cc;
                        int delta = min(max(sg - rg, -16), 16) + 16;
                        float v = s[nt][rid * 2 + cc] + qr[delta];
                        vals[nt * 2 + cc] = v;
                        mx = fmaxf(mx, v);
                    }
            }
            mx = fmaxf(mx, __shfl_xor_sync(0xffffffffu, mx, 1));
            mx = fmaxf(mx, __shfl_xor_sync(0xffffffffu, mx, 2));
            const float mnew = fmaxf(mrow[rid], mx);
            const float alpha = ex2(mrow[rid] - mnew);
            float rs = 0.0f;
#pragma unroll
            for (int j = 0; j < 16; j++) {
                vals[j] = ex2(vals[j] - mnew);
                rs += vals[j];
            }
            rs += __shfl_xor_sync(0xffffffffu, rs, 1);
            rs += __shfl_xor_sync(0xffffffffu, rs, 2);
            lrw[rid] = lrw[rid] * alpha + rs;
            mrow[rid] = mnew;
#pragma unroll
            for (int nt = 0; nt < 8; nt++) {
                o[nt][rid * 2]     *= alpha;
                o[nt][rid * 2 + 1] *= alpha;
            }
#pragma unroll
            for (int j = 0; j < 8; j++) {
                __half2 h = __floats2half2_rn(vals[2 * j], vals[2 * j + 1]);
                ph[rid][j] = *(unsigned*)&h;
            }
        }

        // O += P @ V : P A-fragments straight from ph registers
#pragma unroll
        for (int ks = 0; ks < 4; ks++) {
            unsigned a[4];
            a[0] = ph[0][2 * ks];
            a[1] = ph[1][2 * ks];
            a[2] = ph[0][2 * ks + 1];
            a[3] = ph[1][2 * ks + 1];
            const unsigned ko = ks * 32;
#pragma unroll
            for (int np = 0; np < 4; np++) {
                unsigned vf[4];
                ldsm4(vf, vAddr[np] + ko);
                mma16(o[2 * np],     a, &vf[0]);
                mma16(o[2 * np + 1], a, &vf[2]);
            }
        }
        __syncthreads();   // done reading Ks/Vs; safe to overwrite next iter
    }

    // write attn (fp16) in [t][b][e] layout
    const int b = bh >> 4, h = bh & 15;
#pragma unroll
    for (int rid = 0; rid < 2; rid++) {
        const int t = tq0 + m0 + rid * 8 + g8;
        const float inv = 1.0f / lrw[rid];
#pragma unroll
        for (int nt = 0; nt < 8; nt++) {
            const int d = nt * 8 + 2 * q4;
            *(__half2*)&g_attn[(size_t)(t * BATCH + b) * EMB + h * HD + d] =
                __floats2half2_rn(o[nt][rid * 2] * inv, o[nt][rid * 2 + 1] * inv);
        }
    }
}

// ---------------------------------------------------------------------------
extern "C" void kernel_launch(void* const* d_in, const int* in_sizes, int n_in,
                              void* d_out, int out_size)
{
    (void)in_sizes; (void)n_in; (void)out_size;
    const float* query = (const float*)d_in[0];   // [T,B,E]
    const float* w_in  = (const float*)d_in[1];   // [3E,E]
    const float* b_in  = (const float*)d_in[2];   // [3E]
    const float* relk  = (const float*)d_in[3];   // [33,E]
    const float* w_out = (const float*)d_in[4];   // [E,E]
    const float* b_out = (const float*)d_in[5];   // [E]
    float* out = (float*)d_out;                   // [T,B,E]

    __half *qin, *win, *wout, *attn_ptr;
    cudaGetSymbolAddress((void**)&qin,  g_qin);
    cudaGetSymbolAddress((void**)&win,  g_win);
    cudaGetSymbolAddress((void**)&wout, g_wout);
    cudaGetSymbolAddress((void**)&attn_ptr, g_attn);

    // 0) one-time fp32 -> fp16 pre-conversion (single fused launch)
    cvt_all<<<8192, 256>>>(query, w_in, w_out);

    const size_t gemm_smem = (size_t)6 * GSTG * sizeof(unsigned);  // 110592 B
    cudaFuncSetAttribute(gemm_tc,
                         cudaFuncAttributeMaxDynamicSharedMemorySize,
                         (int)gemm_smem);

    // 1) fused QKV projection -> fp16 head-major q/k/v (V transposed)
    gemm_tc<<<dim3(24, 32), 256, gemm_smem>>>(
        qin, win, b_in, nullptr, 4096, 3072, 1024, 0);

    // 2) flash attention with relative bias (128-row q-tiles)
    const size_t attn_smem =
        (size_t)(128 * 36 + 2 * 64 * 36 + 128 * NREL) * sizeof(unsigned);  // 53760 B
    cudaFuncSetAttribute(attn_tc,
                         cudaFuncAttributeMaxDynamicSharedMemorySize,
                         (int)attn_smem);
    attn_tc<<<dim3(8, 64), 256, attn_smem>>>(relk);

    // 3) output projection (writes fp32 final output)
    gemm_tc<<<dim3(8, 32), 256, gemm_smem>>>(
        attn_ptr, wout, b_out, out, 4096, 1024, 1024, 1);
}

// round 15
// speedup vs baseline: 2.0867x; 1.0001x over previous
#include <cuda_runtime.h>
#include <cuda_fp16.h>

#define T_LEN 1024
#define BATCH 4
#define EMB   1024
#define NH    16
#define HD    64
#define BH    (BATCH*NH)   // 64
#define NREL  33           // 2L+1

// Scratch (static device arrays: allocation-free per harness rules)
__device__ __half g_q[BH * T_LEN * HD];        // fp16, pre-scaled by 0.125*log2e
__device__ __half g_k[BH * T_LEN * HD];        // fp16
__device__ __half g_v[BH * HD * T_LEN];        // fp16, TRANSPOSED [bh][d][t]
__device__ __half g_attn[T_LEN * BATCH * EMB]; // fp16, [t*4+b][e]
__device__ __half g_qin[4096 * 1024];          // fp16(query)
__device__ __half g_win[3072 * 1024];          // fp16(w_in)
__device__ __half g_wout[1024 * 1024];         // fp16(w_out)

__device__ __forceinline__ float ex2(float x) {
    float y;
    asm("ex2.approx.ftz.f32 %0, %1;" : "=f"(y) : "f"(x));
    return y;
}

// m16n8k16 fp16 -> fp32. c aliases d.
__device__ __forceinline__ void mma16(float* c, const unsigned* a, const unsigned* b) {
    asm volatile(
        "mma.sync.aligned.m16n8k16.row.col.f32.f16.f16.f32 "
        "{%0,%1,%2,%3}, {%4,%5,%6,%7}, {%8,%9}, {%0,%1,%2,%3};\n"
        : "+f"(c[0]), "+f"(c[1]), "+f"(c[2]), "+f"(c[3])
        : "r"(a[0]), "r"(a[1]), "r"(a[2]), "r"(a[3]), "r"(b[0]), "r"(b[1]));
}

__device__ __forceinline__ unsigned smem_u32(const void* p) {
    return (unsigned)__cvta_generic_to_shared(p);
}

__device__ __forceinline__ void ldsm4(unsigned* d, unsigned addr) {
    asm volatile(
        "ldmatrix.sync.aligned.m8n8.x4.shared.b16 {%0,%1,%2,%3}, [%4];"
        : "=r"(d[0]), "=r"(d[1]), "=r"(d[2]), "=r"(d[3]) : "r"(addr));
}

__device__ __forceinline__ void cpa16(unsigned dst, const void* src) {
    asm volatile("cp.async.cg.shared.global [%0], [%1], 16;"
                 :: "r"(dst), "l"(src));
}

// ---------------------------------------------------------------------------
// Fused fp32 -> fp16(rn) pre-conversion for query, w_in, w_out (one launch).
// ---------------------------------------------------------------------------
__global__ void __launch_bounds__(256)
cvt_all(const float* __restrict__ q, const float* __restrict__ wi,
        const float* __restrict__ wo)
{
    const int i = blockIdx.x * 256 + threadIdx.x;
    const float* src;
    __half* dst;
    int off;
    if (i < 1048576)      { src = q;  dst = g_qin;  off = i; }
    else if (i < 1835008) { src = wi; dst = g_win;  off = i - 1048576; }
    else                  { src = wo; dst = g_wout; off = i - 1835008; }
    float4 v = ((const float4*)src)[off];
    ((__half2*)dst)[2 * off]     = __floats2half2_rn(v.x, v.y);
    ((__half2*)dst)[2 * off + 1] = __floats2half2_rn(v.z, v.w);
}

// ---------------------------------------------------------------------------
// FP16 TC GEMM (validated round-14): block 128x128, K-chunk 64 halves,
// 8 warps (32m x 64n), cp.async 3-stage ring (one barrier per chunk),
// LDSM fragments, 2 CTAs/SM.
// mode 0: scatter q/k/v fp16 (q scaled by 0.125*log2e, V transposed).
// mode 1: write fp32 Cout.
// ---------------------------------------------------------------------------
#define GSTG (128 * 36)          // words per matrix per stage
#define GSTGB (GSTG * 4)

__global__ void __launch_bounds__(256, 2)
gemm_tc(const __half* __restrict__ A, const __half* __restrict__ B,
        const float* __restrict__ bias, float* __restrict__ Cout,
        int M, int N, int K, int mode)
{
    extern __shared__ unsigned sh[];
    unsigned* As = sh;               // [3][128*36] words
    unsigned* Bs = sh + 3 * GSTG;

    const int tid  = threadIdx.x;
    const int lane = tid & 31;
    const int warp = tid >> 5;
    const int wm   = (warp & 3) * 32;
    const int wn   = (warp >> 2) * 64;
    const int row0 = blockIdx.y * 128;
    const int col0 = blockIdx.x * 128;

    const int lrow = lane & 7;
    const int lb3  = (lane >> 3) & 1;
    const int lb4  = lane >> 4;
    unsigned aAddr[2], bAddr[4];
#pragma unroll
    for (int mt = 0; mt < 2; mt++)
        aAddr[mt] = smem_u32(&As[(wm + mt * 16 + lrow + lb3 * 8) * 36 + lb4 * 4]);
#pragma unroll
    for (int np = 0; np < 4; np++)
        bAddr[np] = smem_u32(&Bs[(wn + np * 16 + lb4 * 8 + lrow) * 36 + lb3 * 4]);

    const unsigned aSm = smem_u32(As);
    const unsigned bSm = smem_u32(Bs);

    float acc[2][8][4];
#pragma unroll
    for (int mt = 0; mt < 2; mt++)
#pragma unroll
        for (int nt = 0; nt < 8; nt++)
#pragma unroll
            for (int f = 0; f < 4; f++) acc[mt][nt][f] = 0.0f;

    const __half* aP = A + (size_t)row0 * K;
    const __half* bP = B + (size_t)col0 * K;

    auto issue = [&](int k0, int st) {
        const unsigned aDst = aSm + (unsigned)st * GSTGB;
        const unsigned bDst = bSm + (unsigned)st * GSTGB;
#pragma unroll
        for (int it = 0; it < 4; it++) {
            const int i = tid + 256 * it;
            const int r = i >> 3, seg = i & 7;
            const unsigned doff = (unsigned)(r * 36 + seg * 4) * 4;
            cpa16(aDst + doff, aP + (size_t)r * K + k0 + seg * 8);
            cpa16(bDst + doff, bP + (size_t)r * K + k0 + seg * 8);
        }
        asm volatile("cp.async.commit_group;");
    };

    const int nC = K >> 6;
    issue(0, 0);
    if (nC > 1) issue(64, 1);

    for (int c = 0; c < nC; c++) {
        const int st = c % 3;
        const unsigned soff = (unsigned)st * GSTGB;

        if (c + 1 < nC) asm volatile("cp.async.wait_group 1;");
        else            asm volatile("cp.async.wait_group 0;");
        __syncthreads();     // chunk c resident; stage (c+2)%3 fully consumed

        if (c + 2 < nC) issue((c + 2) * 64, (c + 2) % 3);

#pragma unroll
        for (int ks = 0; ks < 4; ks++) {
            const unsigned ko = soff + ks * 32;
            unsigned a[2][4], bf[4][4];
            ldsm4(a[0], aAddr[0] + ko);
            ldsm4(a[1], aAddr[1] + ko);
#pragma unroll
            for (int np = 0; np < 4; np++) ldsm4(bf[np], bAddr[np] + ko);
#pragma unroll
            for (int np = 0; np < 4; np++) {
                mma16(acc[0][2 * np],     a[0], &bf[np][0]);
                mma16(acc[1][2 * np],     a[1], &bf[np][0]);
                mma16(acc[0][2 * np + 1], a[0], &bf[np][2]);
                mma16(acc[1][2 * np + 1], a[1], &bf[np][2]);
            }
        }
    }

    // epilogue
    const int q4 = lane & 3;
    const int g8 = lane >> 2;
#pragma unroll
    for (int mt = 0; mt < 2; mt++) {
#pragma unroll
        for (int rr = 0; rr < 2; rr++) {
            const int m = row0 + wm + mt * 16 + g8 + rr * 8;
#pragma unroll
            for (int nt = 0; nt < 8; nt++) {
#pragma unroll
                for (int cc = 0; cc < 2; cc++) {
                    const int n = col0 + wn + nt * 8 + 2 * q4 + cc;
                    float v = acc[mt][nt][rr * 2 + cc] + bias[n];
                    if (mode == 0) {
                        const int sec = n >> 10;
                        const int e = n & 1023;
                        const int h = e >> 6, d = e & 63;
                        const int t = m >> 2, b = m & 3;
                        const int bh = b * NH + h;
                        if (sec == 0)  // 0.125 * log2(e)
                            g_q[(bh * T_LEN + t) * HD + d] =
                                __float2half_rn(v * 0.18033688f);
                        else if (sec == 1)
                            g_k[(bh * T_LEN + t) * HD + d] = __float2half_rn(v);
                        else  // V transposed: [bh][d][t]
                            g_v[((size_t)bh * HD + d) * T_LEN + t] =
                                __float2half_rn(v);
                    } else {
                        Cout[(size_t)m * N + n] = v;
                    }
                }
            }
        }
    }
}

// ---------------------------------------------------------------------------
// FP16 flash attention: 128-row q-tiles, 8 warps x 16 rows, DOUBLE-BUFFERED
// K/V smem (one barrier per k-tile), HOISTED Q fragments (loaded once),
// base-2 softmax, saturation fast path, MMA qr prologue, register-resident P.
// grid = (8 q-tiles, 64 heads), 256 threads. 71.8KB smem.
// ---------------------------------------------------------------------------
__global__ void __launch_bounds__(256)
attn_tc(const float* __restrict__ relk)
{
    extern __shared__ float sm[];
    unsigned* Qs = (unsigned*)sm;             // [128][36]w rows=t, cols=d halves
    unsigned* Ks = Qs + 128 * 36;             // [2][64][36]w rows=s, cols=d
    unsigned* Vs = Ks + 2 * 64 * 36;          // [2][64][36]w rows=d, cols=s
    float* qrs   = (float*)(Vs + 2 * 64 * 36);// [128][33] fp32
    unsigned* Rs = Ks;                        // rel overlay on Ks[0] (consumed first)

    const int tid  = threadIdx.x;
    const int lane = tid & 31;
    const int warp = tid >> 5;                // 0..7
    const int q4   = lane & 3;
    const int g8   = lane >> 2;               // 0..7
    const int bh   = blockIdx.y;
    const int tq0  = blockIdx.x * 128;
    const int m0   = warp * 16;

    const int lrow = lane & 7;
    const int lb3  = (lane >> 3) & 1;
    const int lb4  = lane >> 4;
    const unsigned qAddr = smem_u32(&Qs[(m0 + lrow + lb3 * 8) * 36 + lb4 * 4]);
    unsigned kAddr[2][4], vAddr[2][4], relAddr[3];
#pragma unroll
    for (int st = 0; st < 2; st++)
#pragma unroll
        for (int np = 0; np < 4; np++) {
            kAddr[st][np] = smem_u32(&Ks[(st * 64 + np * 16 + lb4 * 8 + lrow) * 36 + lb3 * 4]);
            vAddr[st][np] = smem_u32(&Vs[(st * 64 + np * 16 + lb4 * 8 + lrow) * 36 + lb3 * 4]);
        }
#pragma unroll
    for (int np = 0; np < 3; np++)
        relAddr[np] = smem_u32(&Rs[(np * 16 + lb4 * 8 + lrow) * 36 + lb3 * 4]);

    // load Q tile (128x64 halves = 1024 uint4)
    {
        const uint4* qb = (const uint4*)(g_q + (size_t)(bh * T_LEN + tq0) * HD);
#pragma unroll
        for (int i = tid; i < 1024; i += 256)
            *(uint4*)&Qs[(i >> 3) * 36 + (i & 7) * 4] = qb[i];
    }
    // relation keys (fp16) into Rs (= Ks[0] region); zero first
    for (int i = tid; i < 64 * 36; i += 256) Rs[i] = 0u;
    __syncthreads();
    {
        __half* relsH = (__half*)Rs;
        for (int i = tid; i < NREL * 64; i += 256) {
            const int j = i >> 6, d = i & 63;
            relsH[j * 72 + d] = __float2half_rn(relk[j * EMB + d]);
        }
    }
    __syncthreads();

    // hoist Q fragments (loop-invariant) and run qr prologue
    unsigned qf[4][4];
#pragma unroll
    for (int ks = 0; ks < 4; ks++) ldsm4(qf[ks], qAddr + ks * 32);

    {
        float sq[6][4];
#pragma unroll
        for (int nt = 0; nt < 6; nt++)
#pragma unroll
            for (int f = 0; f < 4; f++) sq[nt][f] = 0.0f;
#pragma unroll
        for (int ks = 0; ks < 4; ks++) {
#pragma unroll
            for (int np = 0; np < 3; np++) {
                unsigned bf[4];
                ldsm4(bf, relAddr[np] + ks * 32);
                mma16(sq[2 * np],     qf[ks], &bf[0]);
                mma16(sq[2 * np + 1], qf[ks], &bf[2]);
            }
        }
#pragma unroll
        for (int rid = 0; rid < 2; rid++) {
            const int rloc = m0 + rid * 8 + g8;
#pragma unroll
            for (int nt = 0; nt < 6; nt++)
#pragma unroll
                for (int cc = 0; cc < 2; cc++) {
                    const int j = nt * 8 + 2 * q4 + cc;
                    if (j < NREL) qrs[rloc * NREL + j] = sq[nt][rid * 2 + cc];
                }
        }
    }

    const __half* kbase = g_k + (size_t)bh * T_LEN * HD;   // [t][d]
    const __half* vbase = g_v + (size_t)bh * HD * T_LEN;   // [d][t]

    // prefetch tile 0 (512 uint4 per matrix, 2 per thread)
    uint4 pk[2], pv[2];
#pragma unroll
    for (int it = 0; it < 2; it++) {
        const int i = tid + 256 * it;
        const int r = i >> 3, c8 = (i & 7) * 8;
        pk[it] = *(const uint4*)(kbase + (size_t)r * HD + c8);
        pv[it] = *(const uint4*)(vbase + (size_t)r * T_LEN + c8);
    }

    float o[8][4];
#pragma unroll
    for (int nt = 0; nt < 8; nt++)
#pragma unroll
        for (int f = 0; f < 4; f++) o[nt][f] = 0.0f;
    float mrow[2] = {-1e30f, -1e30f};
    float lrw[2]  = {0.0f, 0.0f};

    __syncthreads();   // all warps done reading Rs; qr writes complete

    // store tile 0 into stage 0 (overwrites Rs region)
#pragma unroll
    for (int it = 0; it < 2; it++) {
        const int i = tid + 256 * it;
        const int r = i >> 3, w4 = (i & 7) * 4;
        *(uint4*)&Ks[r * 36 + w4] = pk[it];
        *(uint4*)&Vs[r * 36 + w4] = pv[it];
    }
    __syncthreads();   // stage 0 valid

    for (int kt = 0; kt < 16; kt++) {
        const int s0 = kt * 64;
        const int st = kt & 1;

        // prefetch tile kt+1 into registers
        if (kt + 1 < 16) {
            const __half* kb = kbase + (size_t)(s0 + 64) * HD;
#pragma unroll
            for (int it = 0; it < 2; it++) {
                const int i = tid + 256 * it;
                const int r = i >> 3, c8 = (i & 7) * 8;
                pk[it] = *(const uint4*)(kb + (size_t)r * HD + c8);
                pv[it] = *(const uint4*)(vbase + (size_t)r * T_LEN + s0 + 64 + c8);
            }
        }

        // S = Q @ K^T  (16 rows x 64 cols per warp), Q frags from registers
        float s[8][4];
#pragma unroll
        for (int nt = 0; nt < 8; nt++)
#pragma unroll
            for (int f = 0; f < 4; f++) s[nt][f] = 0.0f;

#pragma unroll
        for (int ks = 0; ks < 4; ks++) {
            const unsigned ko = ks * 32;
#pragma unroll
            for (int np = 0; np < 4; np++) {
                unsigned bf[4];
                ldsm4(bf, kAddr[st][np] + ko);
                mma16(s[2 * np],     qf[ks], &bf[0]);
                mma16(s[2 * np + 1], qf[ks], &bf[2]);
            }
        }

        // bias + online softmax, base-2; pack P directly into A-fragments
        unsigned ph[2][8];
#pragma unroll
        for (int rid = 0; rid < 2; rid++) {
            const int rloc = m0 + rid * 8 + g8;
            const int rg = tq0 + rloc;
            const float* qr = &qrs[rloc * NREL];
            float vals[16];
            float mx = -1e30f;
            if (s0 - rg >= 16) {               // whole tile right-saturated
                const float b32 = qr[32];
#pragma unroll
                for (int nt = 0; nt < 8; nt++)
#pragma unroll
                    for (int cc = 0; cc < 2; cc++) {
                        float v = s[nt][rid * 2 + cc] + b32;
                        vals[nt * 2 + cc] = v;
                        mx = fmaxf(mx, v);
                    }
            } else if (rg - s0 >= 79) {        // whole tile left-saturated
                const float b0 = qr[0];
#pragma unroll
                for (int nt = 0; nt < 8; nt++)
#pragma unroll
                    for (int cc = 0; cc < 2; cc++) {
                        float v = s[nt][rid * 2 + cc] + b0;
                        vals[nt * 2 + cc] = v;
                        mx = fmaxf(mx, v);
                    }
            } else {
#pragma unroll
                for (int nt = 0; nt < 8; nt++)
#pragma unroll
                    for (int cc = 0; cc < 2; cc++) {
                        const int sg = s0 + nt * 8 + 2 * q4 + cc;
                        int delta = min(max(sg - rg, -16), 16) + 16;
                        float v = s[nt][rid * 2 + cc] + qr[delta];
                        vals[nt * 2 + cc] = v;
                        mx = fmaxf(mx, v);
                    }
            }
            mx = fmaxf(mx, __shfl_xor_sync(0xffffffffu, mx, 1));
            mx = fmaxf(mx, __shfl_xor_sync(0xffffffffu, mx, 2));
            const float mnew = fmaxf(mrow[rid], mx);
            const float alpha = ex2(mrow[rid] - mnew);
            float rs = 0.0f;
#pragma unroll
            for (int j = 0; j < 16; j++) {
                vals[j] = ex2(vals[j] - mnew);
                rs += vals[j];
            }
            rs += __shfl_xor_sync(0xffffffffu, rs, 1);
            rs += __shfl_xor_sync(0xffffffffu, rs, 2);
            lrw[rid] = lrw[rid] * alpha + rs;
            mrow[rid] = mnew;
#pragma unroll
            for (int nt = 0; nt < 8; nt++) {
                o[nt][rid * 2]     *= alpha;
                o[nt][rid * 2 + 1] *= alpha;
            }
#pragma unroll
            for (int j = 0; j < 8; j++) {
                __half2 h = __floats2half2_rn(vals[2 * j], vals[2 * j + 1]);
                ph[rid][j] = *(unsigned*)&h;
            }
        }

        // O += P @ V : P A-fragments straight from ph registers
#pragma unroll
        for (int ks = 0; ks < 4; ks++) {
            unsigned a[4];
            a[0] = ph[0][2 * ks];
            a[1] = ph[1][2 * ks];
            a[2] = ph[0][2 * ks + 1];
            a[3] = ph[1][2 * ks + 1];
            const unsigned ko = ks * 32;
#pragma unroll
            for (int np = 0; np < 4; np++) {
                unsigned vf[4];
                ldsm4(vf, vAddr[st][np] + ko);
                mma16(o[2 * np],     a, &vf[0]);
                mma16(o[2 * np + 1], a, &vf[2]);
            }
        }

        // store prefetched tile kt+1 into alternate stage; ONE barrier per kt
        if (kt + 1 < 16) {
            const int sn = st ^ 1;
#pragma unroll
            for (int it = 0; it < 2; it++) {
                const int i = tid + 256 * it;
                const int r = i >> 3, w4 = (i & 7) * 4;
                *(uint4*)&Ks[(sn * 64 + r) * 36 + w4] = pk[it];
                *(uint4*)&Vs[(sn * 64 + r) * 36 + w4] = pv[it];
            }
            __syncthreads();   // stage sn visible; all done reading stage st
        }
    }

    // write attn (fp16) in [t][b][e] layout
    const int b = bh >> 4, h = bh & 15;
#pragma unroll
    for (int rid = 0; rid < 2; rid++) {
        const int t = tq0 + m0 + rid * 8 + g8;
        const float inv = 1.0f / lrw[rid];
#pragma unroll
        for (int nt = 0; nt < 8; nt++) {
            const int d = nt * 8 + 2 * q4;
            *(__half2*)&g_attn[(size_t)(t * BATCH + b) * EMB + h * HD + d] =
                __floats2half2_rn(o[nt][rid * 2] * inv, o[nt][rid * 2 + 1] * inv);
        }
    }
}

// ---------------------------------------------------------------------------
extern "C" void kernel_launch(void* const* d_in, const int* in_sizes, int n_in,
                              void* d_out, int out_size)
{
    (void)in_sizes; (void)n_in; (void)out_size;
    const float* query = (const float*)d_in[0];   // [T,B,E]
    const float* w_in  = (const float*)d_in[1];   // [3E,E]
    const float* b_in  = (const float*)d_in[2];   // [3E]
    const float* relk  = (const float*)d_in[3];   // [33,E]
    const float* w_out = (const float*)d_in[4];   // [E,E]
    const float* b_out = (const float*)d_in[5];   // [E]
    float* out = (float*)d_out;                   // [T,B,E]

    __half *qin, *win, *wout, *attn_ptr;
    cudaGetSymbolAddress((void**)&qin,  g_qin);
    cudaGetSymbolAddress((void**)&win,  g_win);
    cudaGetSymbolAddress((void**)&wout, g_wout);
    cudaGetSymbolAddress((void**)&attn_ptr, g_attn);

    // 0) one-time fp32 -> fp16 pre-conversion (single fused launch)
    cvt_all<<<8192, 256>>>(query, w_in, w_out);

    const size_t gemm_smem = (size_t)6 * GSTG * sizeof(unsigned);  // 110592 B
    cudaFuncSetAttribute(gemm_tc,
                         cudaFuncAttributeMaxDynamicSharedMemorySize,
                         (int)gemm_smem);

    // 1) fused QKV projection -> fp16 head-major q/k/v (V transposed)
    gemm_tc<<<dim3(24, 32), 256, gemm_smem>>>(
        qin, win, b_in, nullptr, 4096, 3072, 1024, 0);

    // 2) flash attention with relative bias (128-row q-tiles, 2-stage K/V)
    const size_t attn_smem =
        (size_t)(128 * 36 + 4 * 64 * 36 + 128 * NREL) * sizeof(unsigned);  // 72192 B
    cudaFuncSetAttribute(attn_tc,
                         cudaFuncAttributeMaxDynamicSharedMemorySize,
                         (int)attn_smem);
    attn_tc<<<dim3(8, 64), 256, attn_smem>>>(relk);

    // 3) output projection (writes fp32 final output)
    gemm_tc<<<dim3(8, 32), 256, gemm_smem>>>(
        attn_ptr, wout, b_out, out, 4096, 1024, 1024, 1);
}

// round 16
// speedup vs baseline: 2.1828x; 1.0461x over previous
#include <cuda_runtime.h>
#include <cuda_fp16.h>

#define T_LEN 1024
#define BATCH 4
#define EMB   1024
#define NH    16
#define HD    64
#define BH    (BATCH*NH)   // 64
#define NREL  33           // 2L+1

// Scratch (static device arrays: allocation-free per harness rules)
__device__ __half g_q[BH * T_LEN * HD];        // fp16, pre-scaled by 0.125*log2e
__device__ __half g_k[BH * T_LEN * HD];        // fp16
__device__ __half g_v[BH * HD * T_LEN];        // fp16, TRANSPOSED [bh][d][t]
__device__ __half g_attn[T_LEN * BATCH * EMB]; // fp16, [t*4+b][e]
__device__ __half g_qin[4096 * 1024];          // fp16(query)
__device__ __half g_win[3072 * 1024];          // fp16(w_in)
__device__ __half g_wout[1024 * 1024];         // fp16(w_out)

__device__ __forceinline__ float ex2(float x) {
    float y;
    asm("ex2.approx.ftz.f32 %0, %1;" : "=f"(y) : "f"(x));
    return y;
}

// m16n8k16 fp16 -> fp32. c aliases d.
__device__ __forceinline__ void mma16(float* c, const unsigned* a, const unsigned* b) {
    asm volatile(
        "mma.sync.aligned.m16n8k16.row.col.f32.f16.f16.f32 "
        "{%0,%1,%2,%3}, {%4,%5,%6,%7}, {%8,%9}, {%0,%1,%2,%3};\n"
        : "+f"(c[0]), "+f"(c[1]), "+f"(c[2]), "+f"(c[3])
        : "r"(a[0]), "r"(a[1]), "r"(a[2]), "r"(a[3]), "r"(b[0]), "r"(b[1]));
}

__device__ __forceinline__ unsigned smem_u32(const void* p) {
    return (unsigned)__cvta_generic_to_shared(p);
}

__device__ __forceinline__ void ldsm4(unsigned* d, unsigned addr) {
    asm volatile(
        "ldmatrix.sync.aligned.m8n8.x4.shared.b16 {%0,%1,%2,%3}, [%4];"
        : "=r"(d[0]), "=r"(d[1]), "=r"(d[2]), "=r"(d[3]) : "r"(addr));
}

__device__ __forceinline__ void cpa16(unsigned dst, const void* src) {
    asm volatile("cp.async.cg.shared.global [%0], [%1], 16;"
                 :: "r"(dst), "l"(src));
}

// ---------------------------------------------------------------------------
// Fused fp32 -> fp16(rn) pre-conversion for query, w_in, w_out (one launch).
// ---------------------------------------------------------------------------
__global__ void __launch_bounds__(256)
cvt_all(const float* __restrict__ q, const float* __restrict__ wi,
        const float* __restrict__ wo)
{
    const int i = blockIdx.x * 256 + threadIdx.x;
    const float* src;
    __half* dst;
    int off;
    if (i < 1048576)      { src = q;  dst = g_qin;  off = i; }
    else if (i < 1835008) { src = wi; dst = g_win;  off = i - 1048576; }
    else                  { src = wo; dst = g_wout; off = i - 1835008; }
    float4 v = ((const float4*)src)[off];
    ((__half2*)dst)[2 * off]     = __floats2half2_rn(v.x, v.y);
    ((__half2*)dst)[2 * off + 1] = __floats2half2_rn(v.z, v.w);
}

// ---------------------------------------------------------------------------
// FP16 TC GEMM: block 128x128, K-chunk 64 halves, 8 warps (32m x 64n),
// cp.async 3-stage ring (one barrier per chunk), SOFTWARE-PIPELINED fragment
// loads (LDSM one step ahead of MMA through the 16-step chunk), 2 CTAs/SM.
// mode 0: scatter q/k/v fp16 (q scaled by 0.125*log2e, V transposed).
// mode 1: write fp32 Cout.
// ---------------------------------------------------------------------------
#define GSTG (128 * 36)          // words per matrix per stage
#define GSTGB (GSTG * 4)

__global__ void __launch_bounds__(256, 2)
gemm_tc(const __half* __restrict__ A, const __half* __restrict__ B,
        const float* __restrict__ bias, float* __restrict__ Cout,
        int M, int N, int K, int mode)
{
    extern __shared__ unsigned sh[];
    unsigned* As = sh;               // [3][128*36] words
    unsigned* Bs = sh + 3 * GSTG;

    const int tid  = threadIdx.x;
    const int lane = tid & 31;
    const int warp = tid >> 5;
    const int wm   = (warp & 3) * 32;
    const int wn   = (warp >> 2) * 64;
    const int row0 = blockIdx.y * 128;
    const int col0 = blockIdx.x * 128;

    const int lrow = lane & 7;
    const int lb3  = (lane >> 3) & 1;
    const int lb4  = lane >> 4;
    unsigned aAddr[2], bAddr[4];
#pragma unroll
    for (int mt = 0; mt < 2; mt++)
        aAddr[mt] = smem_u32(&As[(wm + mt * 16 + lrow + lb3 * 8) * 36 + lb4 * 4]);
#pragma unroll
    for (int np = 0; np < 4; np++)
        bAddr[np] = smem_u32(&Bs[(wn + np * 16 + lb4 * 8 + lrow) * 36 + lb3 * 4]);

    const unsigned aSm = smem_u32(As);
    const unsigned bSm = smem_u32(Bs);

    float acc[2][8][4];
#pragma unroll
    for (int mt = 0; mt < 2; mt++)
#pragma unroll
        for (int nt = 0; nt < 8; nt++)
#pragma unroll
            for (int f = 0; f < 4; f++) acc[mt][nt][f] = 0.0f;

    const __half* aP = A + (size_t)row0 * K;
    const __half* bP = B + (size_t)col0 * K;

    auto issue = [&](int k0, int st) {
        const unsigned aDst = aSm + (unsigned)st * GSTGB;
        const unsigned bDst = bSm + (unsigned)st * GSTGB;
#pragma unroll
        for (int it = 0; it < 4; it++) {
            const int i = tid + 256 * it;
            const int r = i >> 3, seg = i & 7;
            const unsigned doff = (unsigned)(r * 36 + seg * 4) * 4;
            cpa16(aDst + doff, aP + (size_t)r * K + k0 + seg * 8);
            cpa16(bDst + doff, bP + (size_t)r * K + k0 + seg * 8);
        }
        asm volatile("cp.async.commit_group;");
    };

    const int nC = K >> 6;
    issue(0, 0);
    if (nC > 1) issue(64, 1);

    for (int c = 0; c < nC; c++) {
        const int st = c % 3;
        const unsigned soff = (unsigned)st * GSTGB;

        if (c + 1 < nC) asm volatile("cp.async.wait_group 1;");
        else            asm volatile("cp.async.wait_group 0;");
        __syncthreads();     // chunk c resident; stage (c+2)%3 fully consumed

        if (c + 2 < nC) issue((c + 2) * 64, (c + 2) % 3);

        // 16 flattened (ks,np) steps, fragment loads pipelined 1 step ahead.
        unsigned aF[2][2][4];     // [ks&1][mt][4]
        unsigned bF[2][4];        // [s&1][4]
        ldsm4(aF[0][0], aAddr[0] + soff);
        ldsm4(aF[0][1], aAddr[1] + soff);
        ldsm4(bF[0],    bAddr[0] + soff);
#pragma unroll
        for (int s = 0; s < 16; s++) {
            const int ks = s >> 2, np = s & 3;
            const int ns = s + 1;
            if (ns < 16) {
                const int nks = ns >> 2, nnp = ns & 3;
                const unsigned ko = soff + nks * 32;
                if (nnp == 0) {
                    ldsm4(aF[nks & 1][0], aAddr[0] + ko);
                    ldsm4(aF[nks & 1][1], aAddr[1] + ko);
                }
                ldsm4(bF[ns & 1], bAddr[nnp] + ko);
            }
            const unsigned* a0 = aF[ks & 1][0];
            const unsigned* a1 = aF[ks & 1][1];
            const unsigned* bc = bF[s & 1];
            mma16(acc[0][2 * np],     a0, &bc[0]);
            mma16(acc[1][2 * np],     a1, &bc[0]);
            mma16(acc[0][2 * np + 1], a0, &bc[2]);
            mma16(acc[1][2 * np + 1], a1, &bc[2]);
        }
    }

    // epilogue (paired cc stores: half2 for q/k, float2 for Cout)
    const int q4 = lane & 3;
    const int g8 = lane >> 2;
#pragma unroll
    for (int mt = 0; mt < 2; mt++) {
#pragma unroll
        for (int rr = 0; rr < 2; rr++) {
            const int m = row0 + wm + mt * 16 + g8 + rr * 8;
#pragma unroll
            for (int nt = 0; nt < 8; nt++) {
                const int n0 = col0 + wn + nt * 8 + 2 * q4;
                const float v0 = acc[mt][nt][rr * 2]     + bias[n0];
                const float v1 = acc[mt][nt][rr * 2 + 1] + bias[n0 + 1];
                if (mode == 0) {
                    const int sec = n0 >> 10;
                    const int e = n0 & 1023;
                    const int h = e >> 6, d = e & 63;  // d even; d,d+1 same head
                    const int t = m >> 2, b = m & 3;
                    const int bh = b * NH + h;
                    if (sec == 0) {  // 0.125 * log2(e)
                        *(__half2*)&g_q[(bh * T_LEN + t) * HD + d] =
                            __floats2half2_rn(v0 * 0.18033688f, v1 * 0.18033688f);
                    } else if (sec == 1) {
                        *(__half2*)&g_k[(bh * T_LEN + t) * HD + d] =
                            __floats2half2_rn(v0, v1);
                    } else {  // V transposed: [bh][d][t] (scalar, strided)
                        g_v[((size_t)bh * HD + d) * T_LEN + t]       = __float2half_rn(v0);
                        g_v[((size_t)bh * HD + d + 1) * T_LEN + t]   = __float2half_rn(v1);
                    }
                } else {
                    *(float2*)&Cout[(size_t)m * N + n0] = make_float2(v0, v1);
                }
            }
        }
    }
}

// ---------------------------------------------------------------------------
// FP16 flash attention (validated round-15): 128-row q-tiles, 8 warps x 16
// rows, double-buffered K/V smem (one barrier per k-tile), hoisted Q frags,
// base-2 softmax, saturation fast path, MMA qr prologue, register-resident P.
// grid = (8 q-tiles, 64 heads), 256 threads. 71.8KB smem.
// ---------------------------------------------------------------------------
__global__ void __launch_bounds__(256)
attn_tc(const float* __restrict__ relk)
{
    extern __shared__ float sm[];
    unsigned* Qs = (unsigned*)sm;             // [128][36]w rows=t, cols=d halves
    unsigned* Ks = Qs + 128 * 36;             // [2][64][36]w rows=s, cols=d
    unsigned* Vs = Ks + 2 * 64 * 36;          // [2][64][36]w rows=d, cols=s
    float* qrs   = (float*)(Vs + 2 * 64 * 36);// [128][33] fp32
    unsigned* Rs = Ks;                        // rel overlay on Ks[0] (consumed first)

    const int tid  = threadIdx.x;
    const int lane = tid & 31;
    const int warp = tid >> 5;                // 0..7
    const int q4   = lane & 3;
    const int g8   = lane >> 2;               // 0..7
    const int bh   = blockIdx.y;
    const int tq0  = blockIdx.x * 128;
    const int m0   = warp * 16;

    const int lrow = lane & 7;
    const int lb3  = (lane >> 3) & 1;
    const int lb4  = lane >> 4;
    const unsigned qAddr = smem_u32(&Qs[(m0 + lrow + lb3 * 8) * 36 + lb4 * 4]);
    unsigned kAddr[2][4], vAddr[2][4], relAddr[3];
#pragma unroll
    for (int st = 0; st < 2; st++)
#pragma unroll
        for (int np = 0; np < 4; np++) {
            kAddr[st][np] = smem_u32(&Ks[(st * 64 + np * 16 + lb4 * 8 + lrow) * 36 + lb3 * 4]);
            vAddr[st][np] = smem_u32(&Vs[(st * 64 + np * 16 + lb4 * 8 + lrow) * 36 + lb3 * 4]);
        }
#pragma unroll
    for (int np = 0; np < 3; np++)
        relAddr[np] = smem_u32(&Rs[(np * 16 + lb4 * 8 + lrow) * 36 + lb3 * 4]);

    // load Q tile (128x64 halves = 1024 uint4)
    {
        const uint4* qb = (const uint4*)(g_q + (size_t)(bh * T_LEN + tq0) * HD);
#pragma unroll
        for (int i = tid; i < 1024; i += 256)
            *(uint4*)&Qs[(i >> 3) * 36 + (i & 7) * 4] = qb[i];
    }
    // relation keys (fp16) into Rs (= Ks[0] region); zero first
    for (int i = tid; i < 64 * 36; i += 256) Rs[i] = 0u;
    __syncthreads();
    {
        __half* relsH = (__half*)Rs;
        for (int i = tid; i < NREL * 64; i += 256) {
            const int j = i >> 6, d = i & 63;
            relsH[j * 72 + d] = __float2half_rn(relk[j * EMB + d]);
        }
    }
    __syncthreads();

    // hoist Q fragments (loop-invariant) and run qr prologue
    unsigned qf[4][4];
#pragma unroll
    for (int ks = 0; ks < 4; ks++) ldsm4(qf[ks], qAddr + ks * 32);

    {
        float sq[6][4];
#pragma unroll
        for (int nt = 0; nt < 6; nt++)
#pragma unroll
            for (int f = 0; f < 4; f++) sq[nt][f] = 0.0f;
#pragma unroll
        for (int ks = 0; ks < 4; ks++) {
#pragma unroll
            for (int np = 0; np < 3; np++) {
                unsigned bf[4];
                ldsm4(bf, relAddr[np] + ks * 32);
                mma16(sq[2 * np],     qf[ks], &bf[0]);
                mma16(sq[2 * np + 1], qf[ks], &bf[2]);
            }
        }
#pragma unroll
        for (int rid = 0; rid < 2; rid++) {
            const int rloc = m0 + rid * 8 + g8;
#pragma unroll
            for (int nt = 0; nt < 6; nt++)
#pragma unroll
                for (int cc = 0; cc < 2; cc++) {
                    const int j = nt * 8 + 2 * q4 + cc;
                    if (j < NREL) qrs[rloc * NREL + j] = sq[nt][rid * 2 + cc];
                }
        }
    }

    const __half* kbase = g_k + (size_t)bh * T_LEN * HD;   // [t][d]
    const __half* vbase = g_v + (size_t)bh * HD * T_LEN;   // [d][t]

    // prefetch tile 0 (512 uint4 per matrix, 2 per thread)
    uint4 pk[2], pv[2];
#pragma unroll
    for (int it = 0; it < 2; it++) {
        const int i = tid + 256 * it;
        const int r = i >> 3, c8 = (i & 7) * 8;
        pk[it] = *(const uint4*)(kbase + (size_t)r * HD + c8);
        pv[it] = *(const uint4*)(vbase + (size_t)r * T_LEN + c8);
    }

    float o[8][4];
#pragma unroll
    for (int nt = 0; nt < 8; nt++)
#pragma unroll
        for (int f = 0; f < 4; f++) o[nt][f] = 0.0f;
    float mrow[2] = {-1e30f, -1e30f};
    float lrw[2]  = {0.0f, 0.0f};

    __syncthreads();   // all warps done reading Rs; qr writes complete

    // store tile 0 into stage 0 (overwrites Rs region)
#pragma unroll
    for (int it = 0; it < 2; it++) {
        const int i = tid + 256 * it;
        const int r = i >> 3, w4 = (i & 7) * 4;
        *(uint4*)&Ks[r * 36 + w4] = pk[it];
        *(uint4*)&Vs[r * 36 + w4] = pv[it];
    }
    __syncthreads();   // stage 0 valid

    for (int kt = 0; kt < 16; kt++) {
        const int s0 = kt * 64;
        const int st = kt & 1;

        // prefetch tile kt+1 into registers
        if (kt + 1 < 16) {
            const __half* kb = kbase + (size_t)(s0 + 64) * HD;
#pragma unroll
            for (int it = 0; it < 2; it++) {
                const int i = tid + 256 * it;
                const int r = i >> 3, c8 = (i & 7) * 8;
                pk[it] = *(const uint4*)(kb + (size_t)r * HD + c8);
                pv[it] = *(const uint4*)(vbase + (size_t)r * T_LEN + s0 + 64 + c8);
            }
        }

        // S = Q @ K^T  (16 rows x 64 cols per warp), Q frags from registers
        float s[8][4];
#pragma unroll
        for (int nt = 0; nt < 8; nt++)
#pragma unroll
            for (int f = 0; f < 4; f++) s[nt][f] = 0.0f;

#pragma unroll
        for (int ks = 0; ks < 4; ks++) {
            const unsigned ko = ks * 32;
#pragma unroll
            for (int np = 0; np < 4; np++) {
                unsigned bf[4];
                ldsm4(bf, kAddr[st][np] + ko);
                mma16(s[2 * np],     qf[ks], &bf[0]);
                mma16(s[2 * np + 1], qf[ks], &bf[2]);
            }
        }

        // bias + online softmax, base-2; pack P directly into A-fragments
        unsigned ph[2][8];
#pragma unroll
        for (int rid = 0; rid < 2; rid++) {
            const int rloc = m0 + rid * 8 + g8;
            const int rg = tq0 + rloc;
            const float* qr = &qrs[rloc * NREL];
            float vals[16];
            float mx = -1e30f;
            if (s0 - rg >= 16) {               // whole tile right-saturated
                const float b32 = qr[32];
#pragma unroll
                for (int nt = 0; nt < 8; nt++)
#pragma unroll
                    for (int cc = 0; cc < 2; cc++) {
                        float v = s[nt][rid * 2 + cc] + b32;
                        vals[nt * 2 + cc] = v;
                        mx = fmaxf(mx, v);
                    }
            } else if (rg - s0 >= 79) {        // whole tile left-saturated
                const float b0 = qr[0];
#pragma unroll
                for (int nt = 0; nt < 8; nt++)
#pragma unroll
                    for (int cc = 0; cc < 2; cc++) {
                        float v = s[nt][rid * 2 + cc] + b0;
                        vals[nt * 2 + cc] = v;
                        mx = fmaxf(mx, v);
                    }
            } else {
#pragma unroll
                for (int nt = 0; nt < 8; nt++)
#pragma unroll
                    for (int cc = 0; cc < 2; cc++) {
                        const int sg = s0 + nt * 8 + 2 * q4 + cc;
                        int delta = min(max(sg - rg, -16), 16) + 16;
                        float v = s[nt][rid * 2 + cc] + qr[delta];
                        vals[nt * 2 + cc] = v;
                        mx = fmaxf(mx, v);
                    }
            }
            mx = fmaxf(mx, __shfl_xor_sync(0xffffffffu, mx, 1));
            mx = fmaxf(mx, __shfl_xor_sync(0xffffffffu, mx, 2));
            const float mnew = fmaxf(mrow[rid], mx);
            const float alpha = ex2(mrow[rid] - mnew);
            float rs = 0.0f;
#pragma unroll
            for (int j = 0; j < 16; j++) {
                vals[j] = ex2(vals[j] - mnew);
                rs += vals[j];
            }
            rs += __shfl_xor_sync(0xffffffffu, rs, 1);
            rs += __shfl_xor_sync(0xffffffffu, rs, 2);
            lrw[rid] = lrw[rid] * alpha + rs;
            mrow[rid] = mnew;
#pragma unroll
            for (int nt = 0; nt < 8; nt++) {
                o[nt][rid * 2]     *= alpha;
                o[nt][rid * 2 + 1] *= alpha;
            }
#pragma unroll
            for (int j = 0; j < 8; j++) {
                __half2 h = __floats2half2_rn(vals[2 * j], vals[2 * j + 1]);
                ph[rid][j] = *(unsigned*)&h;
            }
        }

        // O += P @ V : P A-fragments straight from ph registers
#pragma unroll
        for (int ks = 0; ks < 4; ks++) {
            unsigned a[4];
            a[0] = ph[0][2 * ks];
            a[1] = ph[1][2 * ks];
            a[2] = ph[0][2 * ks + 1];
            a[3] = ph[1][2 * ks + 1];
            const unsigned ko = ks * 32;
#pragma unroll
            for (int np = 0; np < 4; np++) {
                unsigned vf[4];
                ldsm4(vf, vAddr[st][np] + ko);
                mma16(o[2 * np],     a, &vf[0]);
                mma16(o[2 * np + 1], a, &vf[2]);
            }
        }

        // store prefetched tile kt+1 into alternate stage; ONE barrier per kt
        if (kt + 1 < 16) {
            const int sn = st ^ 1;
#pragma unroll
            for (int it = 0; it < 2; it++) {
                const int i = tid + 256 * it;
                const int r = i >> 3, w4 = (i & 7) * 4;
                *(uint4*)&Ks[(sn * 64 + r) * 36 + w4] = pk[it];
                *(uint4*)&Vs[(sn * 64 + r) * 36 + w4] = pv[it];
            }
            __syncthreads();   // stage sn visible; all done reading stage st
        }
    }

    // write attn (fp16) in [t][b][e] layout
    const int b = bh >> 4, h = bh & 15;
#pragma unroll
    for (int rid = 0; rid < 2; rid++) {
        const int t = tq0 + m0 + rid * 8 + g8;
        const float inv = 1.0f / lrw[rid];
#pragma unroll
        for (int nt = 0; nt < 8; nt++) {
            const int d = nt * 8 + 2 * q4;
            *(__half2*)&g_attn[(size_t)(t * BATCH + b) * EMB + h * HD + d] =
                __floats2half2_rn(o[nt][rid * 2] * inv, o[nt][rid * 2 + 1] * inv);
        }
    }
}

// ---------------------------------------------------------------------------
extern "C" void kernel_launch(void* const* d_in, const int* in_sizes, int n_in,
                              void* d_out, int out_size)
{
    (void)in_sizes; (void)n_in; (void)out_size;
    const float* query = (const float*)d_in[0];   // [T,B,E]
    const float* w_in  = (const float*)d_in[1];   // [3E,E]
    const float* b_in  = (const float*)d_in[2];   // [3E]
    const float* relk  = (const float*)d_in[3];   // [33,E]
    const float* w_out = (const float*)d_in[4];   // [E,E]
    const float* b_out = (const float*)d_in[5];   // [E]
    float* out = (float*)d_out;                   // [T,B,E]

    __half *qin, *win, *wout, *attn_ptr;
    cudaGetSymbolAddress((void**)&qin,  g_qin);
    cudaGetSymbolAddress((void**)&win,  g_win);
    cudaGetSymbolAddress((void**)&wout, g_wout);
    cudaGetSymbolAddress((void**)&attn_ptr, g_attn);

    // 0) one-time fp32 -> fp16 pre-conversion (single fused launch)
    cvt_all<<<8192, 256>>>(query, w_in, w_out);

    const size_t gemm_smem = (size_t)6 * GSTG * sizeof(unsigned);  // 110592 B
    cudaFuncSetAttribute(gemm_tc,
                         cudaFuncAttributeMaxDynamicSharedMemorySize,
                         (int)gemm_smem);

    // 1) fused QKV projection -> fp16 head-major q/k/v (V transposed)
    gemm_tc<<<dim3(24, 32), 256, gemm_smem>>>(
        qin, win, b_in, nullptr, 4096, 3072, 1024, 0);

    // 2) flash attention with relative bias (128-row q-tiles, 2-stage K/V)
    const size_t attn_smem =
        (size_t)(128 * 36 + 4 * 64 * 36 + 128 * NREL) * sizeof(unsigned);  // 72192 B
    cudaFuncSetAttribute(attn_tc,
                         cudaFuncAttributeMaxDynamicSharedMemorySize,
                         (int)attn_smem);
    attn_tc<<<dim3(8, 64), 256, attn_smem>>>(relk);

    // 3) output projection (writes fp32 final output)
    gemm_tc<<<dim3(8, 32), 256, gemm_smem>>>(
        attn_ptr, wout, b_out, out, 4096, 1024, 1024, 1);
}